// round 11
// baseline (speedup 1.0000x reference)
#include <cuda_runtime.h>
#include <cuda_bf16.h>
#include <cuda_fp16.h>
#include <cstdint>
#include <math.h>

// Problem constants
constexpr int cB = 2;
constexpr int cS = 2048;
constexpr int cD = 512;
constexpr int cH = 2048;
constexpr int cL = 4;
constexpr int cV = 32000;
constexpr int cM = cB * cS;  // 4096 rows

// ---------------- static device scratch (no allocation allowed) -------------
__device__ float gX [cM * cD];
__device__ float gQ [cM * cD];
__device__ float gO [cM * cD];
__device__ float gT1[cM * cD];
__device__ float gG1[cM * cD];
__device__ float gFH[cM * cH];
__device__ float gFG[cM * cH];
__device__ float gNL[cM];

// 16-bit weight buffers. emb region of gWhi holds fp16 (logits path);
// layer regions hold bf16 hi (gWhi) / lo (gWlo).
constexpr size_t W_EMB_SZ   = (size_t)cV * cD;
constexpr size_t W_LAYER_SZ = 3 * (size_t)cD * cD + 3 * (size_t)cH * cD;
constexpr size_t W_TOTAL    = W_EMB_SZ + cL * W_LAYER_SZ;

__device__ __nv_bfloat16 gWhi[W_TOTAL];
__device__ __nv_bfloat16 gWlo[W_TOTAL];
__device__ __nv_bfloat16 gAhi[(size_t)cM * cH];
__device__ __nv_bfloat16 gAlo[(size_t)cM * cH];

// ============================ PTX helpers ===================================
__device__ __forceinline__ uint32_t smem_u32(const void* p) {
    uint32_t a;
    asm("{ .reg .u64 t; cvta.to.shared.u64 t, %1; cvt.u32.u64 %0, t; }"
        : "=r"(a) : "l"(p));
    return a;
}
__device__ __forceinline__ void cp16(uint32_t dst, const void* src) {
    asm volatile("cp.async.cg.shared.global [%0], [%1], 16;" :: "r"(dst), "l"(src));
}
#define CP_COMMIT() asm volatile("cp.async.commit_group;" ::: "memory")
#define CP_WAIT(n)  asm volatile("cp.async.wait_group %0;" :: "n"(n) : "memory")

__device__ __forceinline__ void ldsm4(uint32_t* r, uint32_t addr) {
    asm volatile("ldmatrix.sync.aligned.m8n8.x4.shared.b16 {%0,%1,%2,%3}, [%4];"
        : "=r"(r[0]), "=r"(r[1]), "=r"(r[2]), "=r"(r[3]) : "r"(addr));
}
__device__ __forceinline__ void mma16816(float* c, const uint32_t* a, const uint32_t* b) {
    asm volatile(
        "mma.sync.aligned.m16n8k16.row.col.f32.bf16.bf16.f32 "
        "{%0,%1,%2,%3}, {%4,%5,%6,%7}, {%8,%9}, {%0,%1,%2,%3};"
        : "+f"(c[0]), "+f"(c[1]), "+f"(c[2]), "+f"(c[3])
        : "r"(a[0]), "r"(a[1]), "r"(a[2]), "r"(a[3]), "r"(b[0]), "r"(b[1]));
}
__device__ __forceinline__ void mma16816h(float* c, const uint32_t* a, const uint32_t* b) {
    asm volatile(
        "mma.sync.aligned.m16n8k16.row.col.f32.f16.f16.f32 "
        "{%0,%1,%2,%3}, {%4,%5,%6,%7}, {%8,%9}, {%0,%1,%2,%3};"
        : "+f"(c[0]), "+f"(c[1]), "+f"(c[2]), "+f"(c[3])
        : "r"(a[0]), "r"(a[1]), "r"(a[2]), "r"(a[3]), "r"(b[0]), "r"(b[1]));
}

// hi/lo split of 4 floats -> packed bf16x2 writes
__device__ __forceinline__ void split4(float4 v, __nv_bfloat16* hi, __nv_bfloat16* lo,
                                       size_t eoff) {
    __nv_bfloat16 hx = __float2bfloat16_rn(v.x);
    __nv_bfloat16 hy = __float2bfloat16_rn(v.y);
    __nv_bfloat16 hz = __float2bfloat16_rn(v.z);
    __nv_bfloat16 hw = __float2bfloat16_rn(v.w);
    __nv_bfloat16 lx = __float2bfloat16_rn(v.x - __bfloat162float(hx));
    __nv_bfloat16 ly = __float2bfloat16_rn(v.y - __bfloat162float(hy));
    __nv_bfloat16 lz = __float2bfloat16_rn(v.z - __bfloat162float(hz));
    __nv_bfloat16 lw = __float2bfloat16_rn(v.w - __bfloat162float(hw));
    __nv_bfloat162* H = (__nv_bfloat162*)(hi + eoff);
    __nv_bfloat162* L = (__nv_bfloat162*)(lo + eoff);
    H[0] = __nv_bfloat162(hx, hy); H[1] = __nv_bfloat162(hz, hw);
    L[0] = __nv_bfloat162(lx, ly); L[1] = __nv_bfloat162(lz, lw);
}

// ---------------------------------------------------------------------------
// Weight conversion: emb -> single fp16 (logits operand)
__global__ void cvt_f16_k(const float* __restrict__ s,
                          __half* __restrict__ h, int n4) {
    int i = blockIdx.x * blockDim.x + threadIdx.x;
    if (i >= n4) return;
    float4 v = ((const float4*)s)[i];
    __half2* H = (__half2*)(h + (size_t)i * 4);
    H[0] = __halves2half2(__float2half_rn(v.x), __float2half_rn(v.y));
    H[1] = __halves2half2(__float2half_rn(v.z), __float2half_rn(v.w));
}

// All-layer weight conversion in one launch (f4-index space per layer)
constexpr int L4 = 983040;
__global__ void wcvt_layers_k(const float* __restrict__ q, const float* __restrict__ g,
                              const float* __restrict__ o, const float* __restrict__ wh,
                              const float* __restrict__ wg, const float* __restrict__ wo,
                              __nv_bfloat16* __restrict__ hi, __nv_bfloat16* __restrict__ lo) {
    int idx = blockIdx.x * blockDim.x + threadIdx.x;
    if (idx >= cL * L4) return;
    int l = idx / L4;
    int r = idx - l * L4;
    const float* src;
    size_t dst = W_EMB_SZ + (size_t)l * W_LAYER_SZ + (size_t)r * 4;
    if (r < 196608) {
        int t = r / 65536, rr = r - t * 65536;
        const float* bases[3] = {q, g, o};
        src = bases[t] + (size_t)l * 262144 + (size_t)rr * 4;
    } else if (r < 458752) {
        src = wh + (size_t)l * 1048576 + (size_t)(r - 196608) * 4;
    } else if (r < 720896) {
        src = wg + (size_t)l * 1048576 + (size_t)(r - 458752) * 4;
    } else {
        src = wo + (size_t)l * 1048576 + (size_t)(r - 720896) * 4;
    }
    split4(*(const float4*)src, hi, lo, dst);
}

// ---------------------------------------------------------------------------
// bf16x3 mma.sync NT GEMM (layer GEMMs). CTA tile 128 x BN, 8 warps,
// K-chunk 32, cp.async double buffer, one barrier per chunk.
constexpr int PAD = 40;

template<int BN>
__device__ __forceinline__ void stage_chunk(
    const __nv_bfloat16* __restrict__ Ahi, const __nv_bfloat16* __restrict__ Alo,
    const __nv_bfloat16* __restrict__ Bhi, const __nv_bfloat16* __restrict__ Blo,
    int m0, int n0, int Kdim, int kt, uint32_t sbuf, int tid) {
    constexpr int OFF_ALO = 128 * PAD;
    constexpr int OFF_BHI = 256 * PAD;
    constexpr int OFF_BLO = (256 + BN) * PAD;
    #pragma unroll
    for (int it = 0; it < 2; it++) {
        int i = tid + it * 256;
        int r = i >> 2, c = (i & 3) << 3;
        size_t ga = (size_t)(m0 + r) * Kdim + kt + c;
        uint32_t d = sbuf + (uint32_t)(r * PAD + c) * 2;
        cp16(d, Ahi + ga);
        cp16(d + OFF_ALO * 2, Alo + ga);
    }
    #pragma unroll
    for (int it = 0; it < BN / 64; it++) {
        int i = tid + it * 256;
        int r = i >> 2, c = (i & 3) << 3;
        size_t gb = (size_t)(n0 + r) * Kdim + kt + c;
        uint32_t d = sbuf + (uint32_t)(r * PAD + c) * 2;
        cp16(d + OFF_BHI * 2, Bhi + gb);
        cp16(d + OFF_BLO * 2, Blo + gb);
    }
}

template<int BETA, int BN>
__global__ void __launch_bounds__(256) gemm_mma(
    const __nv_bfloat16* __restrict__ Ahi, const __nv_bfloat16* __restrict__ Alo,
    const __nv_bfloat16* __restrict__ Bhi, const __nv_bfloat16* __restrict__ Blo,
    float* __restrict__ C, int Ndim, int Kdim) {
    constexpr int WNT = BN / 2;
    constexpr int NT  = WNT / 8;
    constexpr int NP  = WNT / 16;
    constexpr int OFF_ALO = 128 * PAD;
    constexpr int OFF_BHI = 256 * PAD;
    constexpr int OFF_BLO = (256 + BN) * PAD;
    constexpr int BUF_BYTES = (256 + 2 * BN) * PAD * 2;

    extern __shared__ char smc[];
    const uint32_t sbase = smem_u32(smc);
    const int tid = threadIdx.x;
    const int lane = tid & 31, wid = tid >> 5;
    const int wm = wid & 3, wn = wid >> 2;
    const int m0 = blockIdx.y * 128, n0 = blockIdx.x * BN;
    const int NC = Kdim >> 5;

    float acc[2][NT][4] = {};

    const uint32_t a_lane = (uint32_t)((lane & 15) * PAD + ((lane >> 4) << 3)) * 2;
    const uint32_t b_lane = (uint32_t)(((lane & 7) + ((lane >> 4) << 3)) * PAD
                                       + (((lane >> 3) & 1) << 3)) * 2;

    stage_chunk<BN>(Ahi, Alo, Bhi, Blo, m0, n0, Kdim, 0, sbase, tid);
    CP_COMMIT();

    for (int c = 0; c < NC; c++) {
        const int buf = c & 1;
        CP_WAIT(0);          // chunk c resident in smem
        __syncthreads();     // all warps done with compute(c-1); chunk c visible
        if (c + 1 < NC) {
            stage_chunk<BN>(Ahi, Alo, Bhi, Blo, m0, n0, Kdim, (c + 1) << 5,
                            sbase + (buf ^ 1) * BUF_BYTES, tid);
            CP_COMMIT();
        }

        const uint32_t sb = sbase + buf * BUF_BYTES;
        #pragma unroll
        for (int ks = 0; ks < 32; ks += 16) {
            uint32_t ah[2][4], al[2][4], bh[NP][4], bl[NP][4];
            #pragma unroll
            for (int mt = 0; mt < 2; mt++) {
                uint32_t ar = sb + (uint32_t)(((wm * 32 + mt * 16) * PAD + ks) * 2) + a_lane;
                ldsm4(ah[mt], ar);
                ldsm4(al[mt], ar + OFF_ALO * 2);
            }
            #pragma unroll
            for (int p = 0; p < NP; p++) {
                uint32_t br = sb + (uint32_t)(((wn * WNT + p * 16) * PAD + ks) * 2) + b_lane;
                ldsm4(bh[p], br + OFF_BHI * 2);
                ldsm4(bl[p], br + OFF_BLO * 2);
            }
            #pragma unroll
            for (int mt = 0; mt < 2; mt++)
                #pragma unroll
                for (int j = 0; j < NT; j++) {
                    const uint32_t* bhp = &bh[j >> 1][(j & 1) * 2];
                    const uint32_t* blp = &bl[j >> 1][(j & 1) * 2];
                    mma16816(acc[mt][j], ah[mt], bhp);
                    mma16816(acc[mt][j], ah[mt], blp);
                    mma16816(acc[mt][j], al[mt], bhp);
                }
        }
    }

    #pragma unroll
    for (int mt = 0; mt < 2; mt++) {
        int row = m0 + wm * 32 + mt * 16 + (lane >> 2);
        #pragma unroll
        for (int j = 0; j < NT; j++) {
            int col = n0 + wn * WNT + j * 8 + (lane & 3) * 2;
            float* c0 = C + (size_t)row * Ndim + col;
            float* c1 = C + (size_t)(row + 8) * Ndim + col;
            if (BETA) {
                c0[0] += acc[mt][j][0]; c0[1] += acc[mt][j][1];
                c1[0] += acc[mt][j][2]; c1[1] += acc[mt][j][3];
            } else {
                *(float2*)c0 = make_float2(acc[mt][j][0], acc[mt][j][1]);
                *(float2*)c1 = make_float2(acc[mt][j][2], acc[mt][j][3]);
            }
        }
    }
}

constexpr int GSMEM64  = 2 * (256 + 128) * PAD * 2;   // 61440
constexpr int GSMEM128 = 2 * (256 + 256) * PAD * 2;   // 81920

// ---------------------------------------------------------------------------
// fp16 1-product logits GEMM: C = A @ B^T, both single-rounded fp16.
// CTA tile 128 x 128, 8 warps (warp 32x64), K-chunk 32, double buffer,
// one barrier per chunk.
constexpr int P_OFF_B   = 128 * PAD;
constexpr int P_BUF_BYTES = (128 + 128) * PAD * 2;   // 20480
constexpr int P_GSMEM = 2 * P_BUF_BYTES;             // 40960

__device__ __forceinline__ void stage_1p(
    const __half* __restrict__ Ah, const __half* __restrict__ Bh,
    int m0, int n0, int Kdim, int kt, uint32_t sbuf, int tid) {
    #pragma unroll
    for (int it = 0; it < 2; it++) {
        int i = tid + it * 256;
        int r = i >> 2, c = (i & 3) << 3;
        size_t ga = (size_t)(m0 + r) * Kdim + kt + c;
        cp16(sbuf + (uint32_t)(r * PAD + c) * 2, Ah + ga);
    }
    #pragma unroll
    for (int it = 0; it < 2; it++) {
        int i = tid + it * 256;
        int r = i >> 2, c = (i & 3) << 3;
        size_t gb = (size_t)(n0 + r) * Kdim + kt + c;
        cp16(sbuf + P_OFF_B * 2 + (uint32_t)(r * PAD + c) * 2, Bh + gb);
    }
}

__global__ void __launch_bounds__(256) gemm_1p(
    const __half* __restrict__ Ah, const __half* __restrict__ Bh,
    float* __restrict__ C, int Ndim, int Kdim) {
    extern __shared__ char smc[];
    const uint32_t sbase = smem_u32(smc);
    const int tid = threadIdx.x;
    const int lane = tid & 31, wid = tid >> 5;
    const int wm = wid & 3, wn = wid >> 2;
    const int m0 = blockIdx.y * 128, n0 = blockIdx.x * 128;
    const int NC = Kdim >> 5;

    float acc[2][8][4] = {};

    const uint32_t a_lane = (uint32_t)((lane & 15) * PAD + ((lane >> 4) << 3)) * 2;
    const uint32_t b_lane = (uint32_t)(((lane & 7) + ((lane >> 4) << 3)) * PAD
                                       + (((lane >> 3) & 1) << 3)) * 2;

    stage_1p(Ah, Bh, m0, n0, Kdim, 0, sbase, tid);
    CP_COMMIT();

    for (int c = 0; c < NC; c++) {
        const int buf = c & 1;
        CP_WAIT(0);
        __syncthreads();
        if (c + 1 < NC) {
            stage_1p(Ah, Bh, m0, n0, Kdim, (c + 1) << 5,
                     sbase + (buf ^ 1) * P_BUF_BYTES, tid);
            CP_COMMIT();
        }

        const uint32_t sb = sbase + buf * P_BUF_BYTES;
        #pragma unroll
        for (int ks = 0; ks < 32; ks += 16) {
            uint32_t ah[2][4], bw[4][4];
            #pragma unroll
            for (int mt = 0; mt < 2; mt++) {
                uint32_t ar = sb + (uint32_t)(((wm * 32 + mt * 16) * PAD + ks) * 2) + a_lane;
                ldsm4(ah[mt], ar);
            }
            #pragma unroll
            for (int p = 0; p < 4; p++) {
                uint32_t br = sb + (uint32_t)(((wn * 64 + p * 16) * PAD + ks) * 2) + b_lane;
                ldsm4(bw[p], br + P_OFF_B * 2);
            }
            #pragma unroll
            for (int mt = 0; mt < 2; mt++)
                #pragma unroll
                for (int j = 0; j < 8; j++) {
                    const uint32_t* bp = &bw[j >> 1][(j & 1) * 2];
                    mma16816h(acc[mt][j], ah[mt], bp);
                }
        }
    }

    #pragma unroll
    for (int mt = 0; mt < 2; mt++) {
        int row = m0 + wm * 32 + mt * 16 + (lane >> 2);
        #pragma unroll
        for (int j = 0; j < 8; j++) {
            int col = n0 + wn * 64 + j * 8 + (lane & 3) * 2;
            *(float2*)(C + (size_t)row * Ndim + col) =
                make_float2(acc[mt][j][0], acc[mt][j][1]);
            *(float2*)(C + (size_t)(row + 8) * Ndim + col) =
                make_float2(acc[mt][j][2], acc[mt][j][3]);
        }
    }
}

// ---------------------------------------------------------------------------
// Embedding gather
__global__ void embed_k(const int* __restrict__ tok,
                        const float* __restrict__ emb,
                        float* __restrict__ x) {
    int i = blockIdx.x * blockDim.x + threadIdx.x;
    int row = i / (cD / 4);
    int c   = i % (cD / 4);
    int t = tok[row];
    ((float4*)x)[i] = ((const float4*)(emb + (size_t)t * cD))[c];
}

// RMSNorm + lambda fused: h = rmsnorm(x)*w -> (hi,lo) bf16; nl = logsigmoid(h.lw)
__global__ void rms_lambda_k(const float* __restrict__ x,
                             const float* __restrict__ w,
                             const float* __restrict__ lw,
                             __nv_bfloat16* __restrict__ hi,
                             __nv_bfloat16* __restrict__ lo,
                             float* __restrict__ nlout) {
    int row = blockIdx.x;
    int tid = threadIdx.x;
    float4 v = ((const float4*)(x + (size_t)row * cD))[tid];
    float ss = v.x * v.x + v.y * v.y + v.z * v.z + v.w * v.w;
    #pragma unroll
    for (int o = 16; o; o >>= 1) ss += __shfl_xor_sync(0xFFFFFFFFu, ss, o);
    __shared__ float sred[4];
    if ((tid & 31) == 0) sred[tid >> 5] = ss;
    __syncthreads();
    float sc = rsqrtf((sred[0] + sred[1] + sred[2] + sred[3]) * (1.0f / cD) + 1e-6f);
    float4 wv = ((const float4*)w)[tid];
    float4 h;
    h.x = v.x * sc * wv.x; h.y = v.y * sc * wv.y;
    h.z = v.z * sc * wv.z; h.w = v.w * sc * wv.w;
    split4(h, hi, lo, (size_t)row * cD + tid * 4);
    float4 lv = ((const float4*)lw)[tid];
    float d = h.x * lv.x + h.y * lv.y + h.z * lv.z + h.w * lv.w;
    #pragma unroll
    for (int o = 16; o; o >>= 1) d += __shfl_xor_sync(0xFFFFFFFFu, d, o);
    __shared__ float dred[4];
    if ((tid & 31) == 0) dred[tid >> 5] = d;
    __syncthreads();
    if (tid == 0) {
        float z = dred[0] + dred[1] + dred[2] + dred[3];
        nlout[row] = (z >= 0.f) ? -log1pf(expf(-z)) : (z - log1pf(expf(z)));
    }
}

// RMSNorm -> bf16 (hi,lo)
__global__ void rms_cvt_k(const float* __restrict__ x,
                          const float* __restrict__ w,
                          __nv_bfloat16* __restrict__ hi,
                          __nv_bfloat16* __restrict__ lo) {
    int row = blockIdx.x;
    int tid = threadIdx.x;
    float4 v = ((const float4*)(x + (size_t)row * cD))[tid];
    float ss = v.x * v.x + v.y * v.y + v.z * v.z + v.w * v.w;
    #pragma unroll
    for (int o = 16; o; o >>= 1) ss += __shfl_xor_sync(0xFFFFFFFFu, ss, o);
    __shared__ float sred[4];
    if ((tid & 31) == 0) sred[tid >> 5] = ss;
    __syncthreads();
    float sc = rsqrtf((sred[0] + sred[1] + sred[2] + sred[3]) * (1.0f / cD) + 1e-6f);
    float4 wv = ((const float4*)w)[tid];
    float4 h;
    h.x = v.x * sc * wv.x; h.y = v.y * sc * wv.y;
    h.z = v.z * sc * wv.z; h.w = v.w * sc * wv.w;
    split4(h, hi, lo, (size_t)row * cD + tid * 4);
}

// RMSNorm -> single fp16 (logits activation)
__global__ void rms_cvt_f16s_k(const float* __restrict__ x,
                               const float* __restrict__ w,
                               __half* __restrict__ h16) {
    int row = blockIdx.x;
    int tid = threadIdx.x;
    float4 v = ((const float4*)(x + (size_t)row * cD))[tid];
    float ss = v.x * v.x + v.y * v.y + v.z * v.z + v.w * v.w;
    #pragma unroll
    for (int o = 16; o; o >>= 1) ss += __shfl_xor_sync(0xFFFFFFFFu, ss, o);
    __shared__ float sred[4];
    if ((tid & 31) == 0) sred[tid >> 5] = ss;
    __syncthreads();
    float sc = rsqrtf((sred[0] + sred[1] + sred[2] + sred[3]) * (1.0f / cD) + 1e-6f);
    float4 wv = ((const float4*)w)[tid];
    __half2* H = (__half2*)(h16 + (size_t)row * cD + tid * 4);
    H[0] = __halves2half2(__float2half_rn(v.x * sc * wv.x),
                          __float2half_rn(v.y * sc * wv.y));
    H[1] = __halves2half2(__float2half_rn(v.z * sc * wv.z),
                          __float2half_rn(v.w * sc * wv.w));
}

// Windowed decay attention with one-shot liveness scan.
__global__ void __launch_bounds__(256) attn_k(const float* __restrict__ Q,
                                              const float* __restrict__ NL,
                                              float* __restrict__ O) {
    __shared__ float q_sm[16][64];
    __shared__ float w_sm[16][64];
    __shared__ float nl_sm[16];
    __shared__ int minLive;

    int b  = blockIdx.z;
    int s0 = blockIdx.y * 64;
    int d0 = blockIdx.x * 64;
    int tid = threadIdx.x;
    int tx = tid & 15;
    int ty = tid >> 4;

    float acc[4][4] = {};
    const float* Qb  = Q  + (size_t)b * cS * cD;
    const float* NLb = NL + (size_t)b * cS;

    int t_lo = s0 - 1024; if (t_lo < 0) t_lo = 0;
    int t_hi = s0 + 63;
    int n_tiles = (t_hi - t_lo + 16) >> 4;

    if (tid == 0) minLive = n_tiles - 1;
    __syncthreads();
    if (tid < n_tiles) {
        int t0 = t_lo + tid * 16;
        int live;
        if (t0 + 15 >= s0) {
            live = 1;
        } else {
            float mx = -1e30f;
            #pragma unroll 4
            for (int k = 0; k < 16; k++) mx = fmaxf(mx, NLb[t0 + k]);
            live = (mx * (float)(s0 - (t0 + 15)) > -27.6f);
        }
        if (live) atomicMin(&minLive, tid);
    }
    __syncthreads();
    int t_start = t_lo + minLive * 16;

    for (int t0 = t_start; t0 <= t_hi; t0 += 16) {
        if (tid < 16) {
            int t = t0 + tid;
            nl_sm[tid] = NLb[t < cS ? t : (cS - 1)];
        }
        {
            int k  = tid >> 4;
            int dc = (tid & 15) << 2;
            int t = t0 + k; if (t > cS - 1) t = cS - 1;
            float4 qv = *(const float4*)(Qb + (size_t)t * cD + d0 + dc);
            *(float4*)&q_sm[k][dc] = qv;
        }
        __syncthreads();
        #pragma unroll
        for (int j = 0; j < 4; j++) {
            int idx = tid + j * 256;
            int k  = idx >> 6;
            int sl = idx & 63;
            int t = t0 + k, s = s0 + sl;
            float w = 0.f;
            if (t <= s) w = __expf(nl_sm[k] * (float)(s - t));
            w_sm[k][sl] = w;
        }
        __syncthreads();

        #pragma unroll
        for (int k = 0; k < 16; k++) {
            float4 qv = *(const float4*)&q_sm[k][tx * 4];
            float wv0 = w_sm[k][ty * 4 + 0];
            float wv1 = w_sm[k][ty * 4 + 1];
            float wv2 = w_sm[k][ty * 4 + 2];
            float wv3 = w_sm[k][ty * 4 + 3];
            acc[0][0] += wv0 * qv.x; acc[0][1] += wv0 * qv.y; acc[0][2] += wv0 * qv.z; acc[0][3] += wv0 * qv.w;
            acc[1][0] += wv1 * qv.x; acc[1][1] += wv1 * qv.y; acc[1][2] += wv1 * qv.z; acc[1][3] += wv1 * qv.w;
            acc[2][0] += wv2 * qv.x; acc[2][1] += wv2 * qv.y; acc[2][2] += wv2 * qv.z; acc[2][3] += wv2 * qv.w;
            acc[3][0] += wv3 * qv.x; acc[3][1] += wv3 * qv.y; acc[3][2] += wv3 * qv.z; acc[3][3] += wv3 * qv.w;
        }
        __syncthreads();
    }

    #pragma unroll
    for (int i = 0; i < 4; i++) {
        float4 o4;
        o4.x = acc[i][0]; o4.y = acc[i][1]; o4.z = acc[i][2]; o4.w = acc[i][3];
        *(float4*)(O + (size_t)(b * cS + s0 + ty * 4 + i) * cD + d0 + tx * 4) = o4;
    }
}

// silu(src) -> bf16 (hi, lo)
__global__ void silu_cvt_k(const float* __restrict__ src,
                           __nv_bfloat16* __restrict__ hi,
                           __nv_bfloat16* __restrict__ lo) {
    int i = blockIdx.x * blockDim.x + threadIdx.x;
    float4 v = ((const float4*)src)[i];
    v.x = v.x / (1.f + expf(-v.x));
    v.y = v.y / (1.f + expf(-v.y));
    v.z = v.z / (1.f + expf(-v.z));
    v.w = v.w / (1.f + expf(-v.w));
    split4(v, hi, lo, (size_t)i * 4);
}

// fh * silu(fg) -> bf16 (hi, lo)
__global__ void mulsilu_cvt_k(const float* __restrict__ fh,
                              const float* __restrict__ fg,
                              __nv_bfloat16* __restrict__ hi,
                              __nv_bfloat16* __restrict__ lo) {
    int i = blockIdx.x * blockDim.x + threadIdx.x;
    float4 h = ((const float4*)fh)[i];
    float4 g = ((const float4*)fg)[i];
    h.x *= g.x / (1.f + expf(-g.x));
    h.y *= g.y / (1.f + expf(-g.y));
    h.z *= g.z / (1.f + expf(-g.z));
    h.w *= g.w / (1.f + expf(-g.w));
    split4(h, hi, lo, (size_t)i * 4);
}

// x += a * b
__global__ void addmul_k(float* __restrict__ x, const float* __restrict__ a,
                         const float* __restrict__ b) {
    int i = blockIdx.x * blockDim.x + threadIdx.x;
    float4 xv = ((float4*)x)[i];
    float4 av = ((const float4*)a)[i];
    float4 bv = ((const float4*)b)[i];
    xv.x += av.x * bv.x; xv.y += av.y * bv.y;
    xv.z += av.z * bv.z; xv.w += av.w * bv.w;
    ((float4*)x)[i] = xv;
}

// ---------------------------------------------------------------------------
extern "C" void kernel_launch(void* const* d_in, const int* in_sizes, int n_in,
                              void* d_out, int out_size) {
    const int*   tokens       = (const int*)  d_in[0];
    const float* emb          = (const float*)d_in[1];
    const float* decay_norm_w = (const float*)d_in[2];
    const float* lambda_w     = (const float*)d_in[3];
    const float* quantity_w   = (const float*)d_in[4];
    const float* gate_w       = (const float*)d_in[5];
    const float* output_w     = (const float*)d_in[6];
    const float* ffn_norm_w   = (const float*)d_in[7];
    const float* w_h          = (const float*)d_in[8];
    const float* w_g          = (const float*)d_in[9];
    const float* w_o          = (const float*)d_in[10];
    const float* out_norm_w   = (const float*)d_in[11];
    float* out = (float*)d_out;

    float *X, *Q, *O, *T1, *G1, *FH, *FG, *NL;
    cudaGetSymbolAddress((void**)&X,  gX);
    cudaGetSymbolAddress((void**)&Q,  gQ);
    cudaGetSymbolAddress((void**)&O,  gO);
    cudaGetSymbolAddress((void**)&T1, gT1);
    cudaGetSymbolAddress((void**)&G1, gG1);
    cudaGetSymbolAddress((void**)&FH, gFH);
    cudaGetSymbolAddress((void**)&FG, gFG);
    cudaGetSymbolAddress((void**)&NL, gNL);
    __nv_bfloat16 *Whi, *Wlo, *Ahi, *Alo;
    cudaGetSymbolAddress((void**)&Whi, gWhi);
    cudaGetSymbolAddress((void**)&Wlo, gWlo);
    cudaGetSymbolAddress((void**)&Ahi, gAhi);
    cudaGetSymbolAddress((void**)&Alo, gAlo);

    static bool attr_set = false;
    if (!attr_set) {
        cudaFuncSetAttribute(gemm_mma<0, 64>,  cudaFuncAttributeMaxDynamicSharedMemorySize, GSMEM64);
        cudaFuncSetAttribute(gemm_mma<1, 64>,  cudaFuncAttributeMaxDynamicSharedMemorySize, GSMEM64);
        cudaFuncSetAttribute(gemm_mma<0, 128>, cudaFuncAttributeMaxDynamicSharedMemorySize, GSMEM128);
        cudaFuncSetAttribute(gemm_1p,          cudaFuncAttributeMaxDynamicSharedMemorySize, P_GSMEM);
        attr_set = true;
    }

    // ---- weight conversion (2 launches) ---------------------------------
    // emb -> fp16 single (stored in gWhi emb region, reinterpreted)
    cvt_f16_k<<<(int)(W_EMB_SZ / 4 + 255) / 256, 256>>>(emb, (__half*)Whi,
                                                        (int)(W_EMB_SZ / 4));
    wcvt_layers_k<<<(cL * L4 + 255) / 256, 256>>>(quantity_w, gate_w, output_w,
                                                  w_h, w_g, w_o, Whi, Wlo);

    const int EW_D = (cM * cD / 4) / 256;
    const int EW_H = (cM * cH / 4) / 256;

    embed_k<<<EW_D, 256>>>(tokens, emb, X);

    for (int l = 0; l < cL; l++) {
        size_t base = W_EMB_SZ + (size_t)l * W_LAYER_SZ;
        size_t oQ  = base;
        size_t oG  = base +     (size_t)cD * cD;
        size_t oO  = base + 2 * (size_t)cD * cD;
        size_t oWH = base + 3 * (size_t)cD * cD;
        size_t oWG = oWH + (size_t)cH * cD;
        size_t oWO = oWG + (size_t)cH * cD;

        rms_lambda_k<<<cM, 128>>>(X, decay_norm_w + (size_t)l * cD,
                                  lambda_w + (size_t)l * cD, Ahi, Alo, NL);
        gemm_mma<0, 64><<<dim3(cD / 64, cM / 128), 256, GSMEM64>>>(
            Ahi, Alo, Whi + oQ, Wlo + oQ, Q, cD, cD);
        gemm_mma<0, 64><<<dim3(cD / 64, cM / 128), 256, GSMEM64>>>(
            Ahi, Alo, Whi + oG, Wlo + oG, G1, cD, cD);
        attn_k<<<dim3(cD / 64, cS / 64, cB), 256>>>(Q, NL, O);
        silu_cvt_k<<<EW_D, 256>>>(O, Ahi, Alo);
        gemm_mma<0, 64><<<dim3(cD / 64, cM / 128), 256, GSMEM64>>>(
            Ahi, Alo, Whi + oO, Wlo + oO, T1, cD, cD);
        addmul_k<<<EW_D, 256>>>(X, T1, G1);
        rms_cvt_k<<<cM, 128>>>(X, ffn_norm_w + (size_t)l * cD, Ahi, Alo);
        // FFN up/gate (N=2048): BN=128 — halved staging, grid 16x32 = 512 CTAs
        gemm_mma<0, 128><<<dim3(cH / 128, cM / 128), 256, GSMEM128>>>(
            Ahi, Alo, Whi + oWH, Wlo + oWH, FH, cH, cD);
        gemm_mma<0, 128><<<dim3(cH / 128, cM / 128), 256, GSMEM128>>>(
            Ahi, Alo, Whi + oWG, Wlo + oWG, FG, cH, cD);
        mulsilu_cvt_k<<<EW_H, 256>>>(FH, FG, Ahi, Alo);
        gemm_mma<1, 64><<<dim3(cD / 64, cM / 128), 256, GSMEM64>>>(
            Ahi, Alo, Whi + oWO, Wlo + oWO, X, cD, cH);
    }

    // logits: fp16 1-product (A single fp16, emb single fp16)
    rms_cvt_f16s_k<<<cM, 128>>>(X, out_norm_w, (__half*)Ahi);
    gemm_1p<<<dim3(cV / 128, cM / 128), 256, P_GSMEM>>>(
        (__half*)Ahi, (__half*)Whi, out, cV, cD);
}

// round 13
// speedup vs baseline: 1.0940x; 1.0940x over previous
#include <cuda_runtime.h>
#include <cuda_bf16.h>
#include <cuda_fp16.h>
#include <cstdint>
#include <math.h>

// Problem constants
constexpr int cB = 2;
constexpr int cS = 2048;
constexpr int cD = 512;
constexpr int cH = 2048;
constexpr int cL = 4;
constexpr int cV = 32000;
constexpr int cM = cB * cS;  // 4096 rows

// ---------------- static device scratch (no allocation allowed) -------------
__device__ float gX [cM * cD];
__device__ float gQ [cM * cD];
__device__ float gO [cM * cD];
__device__ float gG1[cM * cD];
__device__ float gFH[cM * cH];
__device__ float gFG[cM * cH];
__device__ float gNL[cM];

// 16-bit weight buffers. emb region of gWhi holds fp16 (logits path);
// layer regions hold bf16 hi (gWhi) / lo (gWlo).
constexpr size_t W_EMB_SZ   = (size_t)cV * cD;
constexpr size_t W_LAYER_SZ = 3 * (size_t)cD * cD + 3 * (size_t)cH * cD;
constexpr size_t W_TOTAL    = W_EMB_SZ + cL * W_LAYER_SZ;

__device__ __nv_bfloat16 gWhi[W_TOTAL];
__device__ __nv_bfloat16 gWlo[W_TOTAL];
__device__ __nv_bfloat16 gAhi[(size_t)cM * cH];
__device__ __nv_bfloat16 gAlo[(size_t)cM * cH];

// ============================ PTX helpers ===================================
__device__ __forceinline__ uint32_t smem_u32(const void* p) {
    uint32_t a;
    asm("{ .reg .u64 t; cvta.to.shared.u64 t, %1; cvt.u32.u64 %0, t; }"
        : "=r"(a) : "l"(p));
    return a;
}
__device__ __forceinline__ void cp16(uint32_t dst, const void* src) {
    asm volatile("cp.async.cg.shared.global [%0], [%1], 16;" :: "r"(dst), "l"(src));
}
#define CP_COMMIT() asm volatile("cp.async.commit_group;" ::: "memory")
#define CP_WAIT(n)  asm volatile("cp.async.wait_group %0;" :: "n"(n) : "memory")

__device__ __forceinline__ void ldsm4(uint32_t* r, uint32_t addr) {
    asm volatile("ldmatrix.sync.aligned.m8n8.x4.shared.b16 {%0,%1,%2,%3}, [%4];"
        : "=r"(r[0]), "=r"(r[1]), "=r"(r[2]), "=r"(r[3]) : "r"(addr));
}
__device__ __forceinline__ void mma16816(float* c, const uint32_t* a, const uint32_t* b) {
    asm volatile(
        "mma.sync.aligned.m16n8k16.row.col.f32.bf16.bf16.f32 "
        "{%0,%1,%2,%3}, {%4,%5,%6,%7}, {%8,%9}, {%0,%1,%2,%3};"
        : "+f"(c[0]), "+f"(c[1]), "+f"(c[2]), "+f"(c[3])
        : "r"(a[0]), "r"(a[1]), "r"(a[2]), "r"(a[3]), "r"(b[0]), "r"(b[1]));
}
__device__ __forceinline__ void mma16816h(float* c, const uint32_t* a, const uint32_t* b) {
    asm volatile(
        "mma.sync.aligned.m16n8k16.row.col.f32.f16.f16.f32 "
        "{%0,%1,%2,%3}, {%4,%5,%6,%7}, {%8,%9}, {%0,%1,%2,%3};"
        : "+f"(c[0]), "+f"(c[1]), "+f"(c[2]), "+f"(c[3])
        : "r"(a[0]), "r"(a[1]), "r"(a[2]), "r"(a[3]), "r"(b[0]), "r"(b[1]));
}

// hi/lo split of 4 floats -> packed bf16x2 writes
__device__ __forceinline__ void split4(float4 v, __nv_bfloat16* hi, __nv_bfloat16* lo,
                                       size_t eoff) {
    __nv_bfloat16 hx = __float2bfloat16_rn(v.x);
    __nv_bfloat16 hy = __float2bfloat16_rn(v.y);
    __nv_bfloat16 hz = __float2bfloat16_rn(v.z);
    __nv_bfloat16 hw = __float2bfloat16_rn(v.w);
    __nv_bfloat16 lx = __float2bfloat16_rn(v.x - __bfloat162float(hx));
    __nv_bfloat16 ly = __float2bfloat16_rn(v.y - __bfloat162float(hy));
    __nv_bfloat16 lz = __float2bfloat16_rn(v.z - __bfloat162float(hz));
    __nv_bfloat16 lw = __float2bfloat16_rn(v.w - __bfloat162float(hw));
    __nv_bfloat162* H = (__nv_bfloat162*)(hi + eoff);
    __nv_bfloat162* L = (__nv_bfloat162*)(lo + eoff);
    H[0] = __nv_bfloat162(hx, hy); H[1] = __nv_bfloat162(hz, hw);
    L[0] = __nv_bfloat162(lx, ly); L[1] = __nv_bfloat162(lz, lw);
}

// ---------------------------------------------------------------------------
// Weight conversion: emb -> single fp16 (logits operand)
__global__ void cvt_f16_k(const float* __restrict__ s,
                          __half* __restrict__ h, int n4) {
    int i = blockIdx.x * blockDim.x + threadIdx.x;
    if (i >= n4) return;
    float4 v = ((const float4*)s)[i];
    __half2* H = (__half2*)(h + (size_t)i * 4);
    H[0] = __halves2half2(__float2half_rn(v.x), __float2half_rn(v.y));
    H[1] = __halves2half2(__float2half_rn(v.z), __float2half_rn(v.w));
}

// All-layer weight conversion in one launch (f4-index space per layer)
constexpr int L4 = 983040;
__global__ void wcvt_layers_k(const float* __restrict__ q, const float* __restrict__ g,
                              const float* __restrict__ o, const float* __restrict__ wh,
                              const float* __restrict__ wg, const float* __restrict__ wo,
                              __nv_bfloat16* __restrict__ hi, __nv_bfloat16* __restrict__ lo) {
    int idx = blockIdx.x * blockDim.x + threadIdx.x;
    if (idx >= cL * L4) return;
    int l = idx / L4;
    int r = idx - l * L4;
    const float* src;
    size_t dst = W_EMB_SZ + (size_t)l * W_LAYER_SZ + (size_t)r * 4;
    if (r < 196608) {
        int t = r / 65536, rr = r - t * 65536;
        const float* bases[3] = {q, g, o};
        src = bases[t] + (size_t)l * 262144 + (size_t)rr * 4;
    } else if (r < 458752) {
        src = wh + (size_t)l * 1048576 + (size_t)(r - 196608) * 4;
    } else if (r < 720896) {
        src = wg + (size_t)l * 1048576 + (size_t)(r - 458752) * 4;
    } else {
        src = wo + (size_t)l * 1048576 + (size_t)(r - 720896) * 4;
    }
    split4(*(const float4*)src, hi, lo, dst);
}

// ---------------------------------------------------------------------------
// bf16x3 mma.sync NT GEMM (layer GEMMs). CTA tile 128 x BN=64, 8 warps,
// K-chunk 32, cp.async double buffer, one barrier per chunk.
// EPI: 0 = store (dual-output: C2/nSplit select buffer by n0),
//      1 = C += acc, 2 = C += acc * gate (gate row stride = Ndim).
constexpr int PAD = 40;

template<int BN>
__device__ __forceinline__ void stage_chunk(
    const __nv_bfloat16* __restrict__ Ahi, const __nv_bfloat16* __restrict__ Alo,
    const __nv_bfloat16* __restrict__ Bhi, const __nv_bfloat16* __restrict__ Blo,
    int m0, int n0, int Kdim, int kt, uint32_t sbuf, int tid) {
    constexpr int OFF_ALO = 128 * PAD;
    constexpr int OFF_BHI = 256 * PAD;
    constexpr int OFF_BLO = (256 + BN) * PAD;
    #pragma unroll
    for (int it = 0; it < 2; it++) {
        int i = tid + it * 256;
        int r = i >> 2, c = (i & 3) << 3;
        size_t ga = (size_t)(m0 + r) * Kdim + kt + c;
        uint32_t d = sbuf + (uint32_t)(r * PAD + c) * 2;
        cp16(d, Ahi + ga);
        cp16(d + OFF_ALO * 2, Alo + ga);
    }
    #pragma unroll
    for (int it = 0; it < BN / 64; it++) {
        int i = tid + it * 256;
        int r = i >> 2, c = (i & 3) << 3;
        size_t gb = (size_t)(n0 + r) * Kdim + kt + c;
        uint32_t d = sbuf + (uint32_t)(r * PAD + c) * 2;
        cp16(d + OFF_BHI * 2, Bhi + gb);
        cp16(d + OFF_BLO * 2, Blo + gb);
    }
}

template<int EPI, int BN>
__global__ void __launch_bounds__(256) gemm_mma(
    const __nv_bfloat16* __restrict__ Ahi, const __nv_bfloat16* __restrict__ Alo,
    const __nv_bfloat16* __restrict__ Bhi, const __nv_bfloat16* __restrict__ Blo,
    float* __restrict__ C, float* __restrict__ C2, int nSplit,
    const float* __restrict__ gate, int Ndim, int Kdim) {
    constexpr int WNT = BN / 2;
    constexpr int NT  = WNT / 8;
    constexpr int NP  = WNT / 16;
    constexpr int OFF_ALO = 128 * PAD;
    constexpr int OFF_BHI = 256 * PAD;
    constexpr int OFF_BLO = (256 + BN) * PAD;
    constexpr int BUF_BYTES = (256 + 2 * BN) * PAD * 2;

    extern __shared__ char smc[];
    const uint32_t sbase = smem_u32(smc);
    const int tid = threadIdx.x;
    const int lane = tid & 31, wid = tid >> 5;
    const int wm = wid & 3, wn = wid >> 2;
    const int m0 = blockIdx.y * 128, n0 = blockIdx.x * BN;
    const int NC = Kdim >> 5;

    float acc[2][NT][4] = {};

    const uint32_t a_lane = (uint32_t)((lane & 15) * PAD + ((lane >> 4) << 3)) * 2;
    const uint32_t b_lane = (uint32_t)(((lane & 7) + ((lane >> 4) << 3)) * PAD
                                       + (((lane >> 3) & 1) << 3)) * 2;

    stage_chunk<BN>(Ahi, Alo, Bhi, Blo, m0, n0, Kdim, 0, sbase, tid);
    CP_COMMIT();

    for (int c = 0; c < NC; c++) {
        const int buf = c & 1;
        CP_WAIT(0);          // chunk c resident in smem
        __syncthreads();     // all warps done with compute(c-1); chunk c visible
        if (c + 1 < NC) {
            stage_chunk<BN>(Ahi, Alo, Bhi, Blo, m0, n0, Kdim, (c + 1) << 5,
                            sbase + (buf ^ 1) * BUF_BYTES, tid);
            CP_COMMIT();
        }

        const uint32_t sb = sbase + buf * BUF_BYTES;
        #pragma unroll
        for (int ks = 0; ks < 32; ks += 16) {
            uint32_t ah[2][4], al[2][4], bh[NP][4], bl[NP][4];
            #pragma unroll
            for (int mt = 0; mt < 2; mt++) {
                uint32_t ar = sb + (uint32_t)(((wm * 32 + mt * 16) * PAD + ks) * 2) + a_lane;
                ldsm4(ah[mt], ar);
                ldsm4(al[mt], ar + OFF_ALO * 2);
            }
            #pragma unroll
            for (int p = 0; p < NP; p++) {
                uint32_t br = sb + (uint32_t)(((wn * WNT + p * 16) * PAD + ks) * 2) + b_lane;
                ldsm4(bh[p], br + OFF_BHI * 2);
                ldsm4(bl[p], br + OFF_BLO * 2);
            }
            #pragma unroll
            for (int mt = 0; mt < 2; mt++)
                #pragma unroll
                for (int j = 0; j < NT; j++) {
                    const uint32_t* bhp = &bh[j >> 1][(j & 1) * 2];
                    const uint32_t* blp = &bl[j >> 1][(j & 1) * 2];
                    mma16816(acc[mt][j], ah[mt], bhp);
                    mma16816(acc[mt][j], ah[mt], blp);
                    mma16816(acc[mt][j], al[mt], bhp);
                }
        }
    }

    // dual-output select (uniform per CTA; BN=64 never straddles nSplit)
    float* Cout = C;
    int nbase = n0;
    if (EPI == 0 && C2 != nullptr && n0 >= nSplit) { Cout = C2; nbase = n0 - nSplit; }

    #pragma unroll
    for (int mt = 0; mt < 2; mt++) {
        int row = m0 + wm * 32 + mt * 16 + (lane >> 2);
        #pragma unroll
        for (int j = 0; j < NT; j++) {
            int col = nbase + wn * WNT + j * 8 + (lane & 3) * 2;
            float* c0 = Cout + (size_t)row * Ndim + col;
            float* c1 = Cout + (size_t)(row + 8) * Ndim + col;
            if (EPI == 1) {
                c0[0] += acc[mt][j][0]; c0[1] += acc[mt][j][1];
                c1[0] += acc[mt][j][2]; c1[1] += acc[mt][j][3];
            } else if (EPI == 2) {
                const float* g0 = gate + (size_t)row * Ndim + col;
                const float* g1 = gate + (size_t)(row + 8) * Ndim + col;
                c0[0] += acc[mt][j][0] * g0[0]; c0[1] += acc[mt][j][1] * g0[1];
                c1[0] += acc[mt][j][2] * g1[0]; c1[1] += acc[mt][j][3] * g1[1];
            } else {
                *(float2*)c0 = make_float2(acc[mt][j][0], acc[mt][j][1]);
                *(float2*)c1 = make_float2(acc[mt][j][2], acc[mt][j][3]);
            }
        }
    }
}

constexpr int GSMEM64 = 2 * (256 + 128) * PAD * 2;   // 61440

// ---------------------------------------------------------------------------
// fp16 1-product logits GEMM: C = A @ B^T, both single-rounded fp16.
// CTA tile 128 x 128, 8 warps (warp 32x64), K-chunk 32, double buffer,
// one barrier per chunk.
constexpr int P_OFF_B   = 128 * PAD;
constexpr int P_BUF_BYTES = (128 + 128) * PAD * 2;   // 20480
constexpr int P_GSMEM = 2 * P_BUF_BYTES;             // 40960

__device__ __forceinline__ void stage_1p(
    const __half* __restrict__ Ah, const __half* __restrict__ Bh,
    int m0, int n0, int Kdim, int kt, uint32_t sbuf, int tid) {
    #pragma unroll
    for (int it = 0; it < 2; it++) {
        int i = tid + it * 256;
        int r = i >> 2, c = (i & 3) << 3;
        size_t ga = (size_t)(m0 + r) * Kdim + kt + c;
        cp16(sbuf + (uint32_t)(r * PAD + c) * 2, Ah + ga);
    }
    #pragma unroll
    for (int it = 0; it < 2; it++) {
        int i = tid + it * 256;
        int r = i >> 2, c = (i & 3) << 3;
        size_t gb = (size_t)(n0 + r) * Kdim + kt + c;
        cp16(sbuf + P_OFF_B * 2 + (uint32_t)(r * PAD + c) * 2, Bh + gb);
    }
}

__global__ void __launch_bounds__(256) gemm_1p(
    const __half* __restrict__ Ah, const __half* __restrict__ Bh,
    float* __restrict__ C, int Ndim, int Kdim) {
    extern __shared__ char smc[];
    const uint32_t sbase = smem_u32(smc);
    const int tid = threadIdx.x;
    const int lane = tid & 31, wid = tid >> 5;
    const int wm = wid & 3, wn = wid >> 2;
    const int m0 = blockIdx.y * 128, n0 = blockIdx.x * 128;
    const int NC = Kdim >> 5;

    float acc[2][8][4] = {};

    const uint32_t a_lane = (uint32_t)((lane & 15) * PAD + ((lane >> 4) << 3)) * 2;
    const uint32_t b_lane = (uint32_t)(((lane & 7) + ((lane >> 4) << 3)) * PAD
                                       + (((lane >> 3) & 1) << 3)) * 2;

    stage_1p(Ah, Bh, m0, n0, Kdim, 0, sbase, tid);
    CP_COMMIT();

    for (int c = 0; c < NC; c++) {
        const int buf = c & 1;
        CP_WAIT(0);
        __syncthreads();
        if (c + 1 < NC) {
            stage_1p(Ah, Bh, m0, n0, Kdim, (c + 1) << 5,
                     sbase + (buf ^ 1) * P_BUF_BYTES, tid);
            CP_COMMIT();
        }

        const uint32_t sb = sbase + buf * P_BUF_BYTES;
        #pragma unroll
        for (int ks = 0; ks < 32; ks += 16) {
            uint32_t ah[2][4], bw[4][4];
            #pragma unroll
            for (int mt = 0; mt < 2; mt++) {
                uint32_t ar = sb + (uint32_t)(((wm * 32 + mt * 16) * PAD + ks) * 2) + a_lane;
                ldsm4(ah[mt], ar);
            }
            #pragma unroll
            for (int p = 0; p < 4; p++) {
                uint32_t br = sb + (uint32_t)(((wn * 64 + p * 16) * PAD + ks) * 2) + b_lane;
                ldsm4(bw[p], br + P_OFF_B * 2);
            }
            #pragma unroll
            for (int mt = 0; mt < 2; mt++)
                #pragma unroll
                for (int j = 0; j < 8; j++) {
                    const uint32_t* bp = &bw[j >> 1][(j & 1) * 2];
                    mma16816h(acc[mt][j], ah[mt], bp);
                }
        }
    }

    #pragma unroll
    for (int mt = 0; mt < 2; mt++) {
        int row = m0 + wm * 32 + mt * 16 + (lane >> 2);
        #pragma unroll
        for (int j = 0; j < 8; j++) {
            int col = n0 + wn * 64 + j * 8 + (lane & 3) * 2;
            *(float2*)(C + (size_t)row * Ndim + col) =
                make_float2(acc[mt][j][0], acc[mt][j][1]);
            *(float2*)(C + (size_t)(row + 8) * Ndim + col) =
                make_float2(acc[mt][j][2], acc[mt][j][3]);
        }
    }
}

// ---------------------------------------------------------------------------
// Embedding gather
__global__ void embed_k(const int* __restrict__ tok,
                        const float* __restrict__ emb,
                        float* __restrict__ x) {
    int i = blockIdx.x * blockDim.x + threadIdx.x;
    int row = i / (cD / 4);
    int c   = i % (cD / 4);
    int t = tok[row];
    ((float4*)x)[i] = ((const float4*)(emb + (size_t)t * cD))[c];
}

// RMSNorm + lambda fused: h = rmsnorm(x)*w -> (hi,lo) bf16; nl = logsigmoid(h.lw)
__global__ void rms_lambda_k(const float* __restrict__ x,
                             const float* __restrict__ w,
                             const float* __restrict__ lw,
                             __nv_bfloat16* __restrict__ hi,
                             __nv_bfloat16* __restrict__ lo,
                             float* __restrict__ nlout) {
    int row = blockIdx.x;
    int tid = threadIdx.x;
    float4 v = ((const float4*)(x + (size_t)row * cD))[tid];
    float ss = v.x * v.x + v.y * v.y + v.z * v.z + v.w * v.w;
    #pragma unroll
    for (int o = 16; o; o >>= 1) ss += __shfl_xor_sync(0xFFFFFFFFu, ss, o);
    __shared__ float sred[4];
    if ((tid & 31) == 0) sred[tid >> 5] = ss;
    __syncthreads();
    float sc = rsqrtf((sred[0] + sred[1] + sred[2] + sred[3]) * (1.0f / cD) + 1e-6f);
    float4 wv = ((const float4*)w)[tid];
    float4 h;
    h.x = v.x * sc * wv.x; h.y = v.y * sc * wv.y;
    h.z = v.z * sc * wv.z; h.w = v.w * sc * wv.w;
    split4(h, hi, lo, (size_t)row * cD + tid * 4);
    float4 lv = ((const float4*)lw)[tid];
    float d = h.x * lv.x + h.y * lv.y + h.z * lv.z + h.w * lv.w;
    #pragma unroll
    for (int o = 16; o; o >>= 1) d += __shfl_xor_sync(0xFFFFFFFFu, d, o);
    __shared__ float dred[4];
    if ((tid & 31) == 0) dred[tid >> 5] = d;
    __syncthreads();
    if (tid == 0) {
        float z = dred[0] + dred[1] + dred[2] + dred[3];
        nlout[row] = (z >= 0.f) ? -log1pf(expf(-z)) : (z - log1pf(expf(z)));
    }
}

// RMSNorm -> bf16 (hi,lo)
__global__ void rms_cvt_k(const float* __restrict__ x,
                          const float* __restrict__ w,
                          __nv_bfloat16* __restrict__ hi,
                          __nv_bfloat16* __restrict__ lo) {
    int row = blockIdx.x;
    int tid = threadIdx.x;
    float4 v = ((const float4*)(x + (size_t)row * cD))[tid];
    float ss = v.x * v.x + v.y * v.y + v.z * v.z + v.w * v.w;
    #pragma unroll
    for (int o = 16; o; o >>= 1) ss += __shfl_xor_sync(0xFFFFFFFFu, ss, o);
    __shared__ float sred[4];
    if ((tid & 31) == 0) sred[tid >> 5] = ss;
    __syncthreads();
    float sc = rsqrtf((sred[0] + sred[1] + sred[2] + sred[3]) * (1.0f / cD) + 1e-6f);
    float4 wv = ((const float4*)w)[tid];
    float4 h;
    h.x = v.x * sc * wv.x; h.y = v.y * sc * wv.y;
    h.z = v.z * sc * wv.z; h.w = v.w * sc * wv.w;
    split4(h, hi, lo, (size_t)row * cD + tid * 4);
}

// RMSNorm -> single fp16 (logits activation)
__global__ void rms_cvt_f16s_k(const float* __restrict__ x,
                               const float* __restrict__ w,
                               __half* __restrict__ h16) {
    int row = blockIdx.x;
    int tid = threadIdx.x;
    float4 v = ((const float4*)(x + (size_t)row * cD))[tid];
    float ss = v.x * v.x + v.y * v.y + v.z * v.z + v.w * v.w;
    #pragma unroll
    for (int o = 16; o; o >>= 1) ss += __shfl_xor_sync(0xFFFFFFFFu, ss, o);
    __shared__ float sred[4];
    if ((tid & 31) == 0) sred[tid >> 5] = ss;
    __syncthreads();
    float sc = rsqrtf((sred[0] + sred[1] + sred[2] + sred[3]) * (1.0f / cD) + 1e-6f);
    float4 wv = ((const float4*)w)[tid];
    __half2* H = (__half2*)(h16 + (size_t)row * cD + tid * 4);
    H[0] = __halves2half2(__float2half_rn(v.x * sc * wv.x),
                          __float2half_rn(v.y * sc * wv.y));
    H[1] = __halves2half2(__float2half_rn(v.z * sc * wv.z),
                          __float2half_rn(v.w * sc * wv.w));
}

// Windowed decay attention with one-shot liveness scan.
__global__ void __launch_bounds__(256) attn_k(const float* __restrict__ Q,
                                              const float* __restrict__ NL,
                                              float* __restrict__ O) {
    __shared__ float q_sm[16][64];
    __shared__ float w_sm[16][64];
    __shared__ float nl_sm[16];
    __shared__ int minLive;

    int b  = blockIdx.z;
    int s0 = blockIdx.y * 64;
    int d0 = blockIdx.x * 64;
    int tid = threadIdx.x;
    int tx = tid & 15;
    int ty = tid >> 4;

    float acc[4][4] = {};
    const float* Qb  = Q  + (size_t)b * cS * cD;
    const float* NLb = NL + (size_t)b * cS;

    int t_lo = s0 - 1024; if (t_lo < 0) t_lo = 0;
    int t_hi = s0 + 63;
    int n_tiles = (t_hi - t_lo + 16) >> 4;

    if (tid == 0) minLive = n_tiles - 1;
    __syncthreads();
    if (tid < n_tiles) {
        int t0 = t_lo + tid * 16;
        int live;
        if (t0 + 15 >= s0) {
            live = 1;
        } else {
            float mx = -1e30f;
            #pragma unroll 4
            for (int k = 0; k < 16; k++) mx = fmaxf(mx, NLb[t0 + k]);
            live = (mx * (float)(s0 - (t0 + 15)) > -27.6f);
        }
        if (live) atomicMin(&minLive, tid);
    }
    __syncthreads();
    int t_start = t_lo + minLive * 16;

    for (int t0 = t_start; t0 <= t_hi; t0 += 16) {
        if (tid < 16) {
            int t = t0 + tid;
            nl_sm[tid] = NLb[t < cS ? t : (cS - 1)];
        }
        {
            int k  = tid >> 4;
            int dc = (tid & 15) << 2;
            int t = t0 + k; if (t > cS - 1) t = cS - 1;
            float4 qv = *(const float4*)(Qb + (size_t)t * cD + d0 + dc);
            *(float4*)&q_sm[k][dc] = qv;
        }
        __syncthreads();
        #pragma unroll
        for (int j = 0; j < 4; j++) {
            int idx = tid + j * 256;
            int k  = idx >> 6;
            int sl = idx & 63;
            int t = t0 + k, s = s0 + sl;
            float w = 0.f;
            if (t <= s) w = __expf(nl_sm[k] * (float)(s - t));
            w_sm[k][sl] = w;
        }
        __syncthreads();

        #pragma unroll
        for (int k = 0; k < 16; k++) {
            float4 qv = *(const float4*)&q_sm[k][tx * 4];
            float wv0 = w_sm[k][ty * 4 + 0];
            float wv1 = w_sm[k][ty * 4 + 1];
            float wv2 = w_sm[k][ty * 4 + 2];
            float wv3 = w_sm[k][ty * 4 + 3];
            acc[0][0] += wv0 * qv.x; acc[0][1] += wv0 * qv.y; acc[0][2] += wv0 * qv.z; acc[0][3] += wv0 * qv.w;
            acc[1][0] += wv1 * qv.x; acc[1][1] += wv1 * qv.y; acc[1][2] += wv1 * qv.z; acc[1][3] += wv1 * qv.w;
            acc[2][0] += wv2 * qv.x; acc[2][1] += wv2 * qv.y; acc[2][2] += wv2 * qv.z; acc[2][3] += wv2 * qv.w;
            acc[3][0] += wv3 * qv.x; acc[3][1] += wv3 * qv.y; acc[3][2] += wv3 * qv.z; acc[3][3] += wv3 * qv.w;
        }
        __syncthreads();
    }

    #pragma unroll
    for (int i = 0; i < 4; i++) {
        float4 o4;
        o4.x = acc[i][0]; o4.y = acc[i][1]; o4.z = acc[i][2]; o4.w = acc[i][3];
        *(float4*)(O + (size_t)(b * cS + s0 + ty * 4 + i) * cD + d0 + tx * 4) = o4;
    }
}

// silu(src) -> bf16 (hi, lo)
__global__ void silu_cvt_k(const float* __restrict__ src,
                           __nv_bfloat16* __restrict__ hi,
                           __nv_bfloat16* __restrict__ lo) {
    int i = blockIdx.x * blockDim.x + threadIdx.x;
    float4 v = ((const float4*)src)[i];
    v.x = v.x / (1.f + expf(-v.x));
    v.y = v.y / (1.f + expf(-v.y));
    v.z = v.z / (1.f + expf(-v.z));
    v.w = v.w / (1.f + expf(-v.w));
    split4(v, hi, lo, (size_t)i * 4);
}

// fh * silu(fg) -> bf16 (hi, lo)
__global__ void mulsilu_cvt_k(const float* __restrict__ fh,
                              const float* __restrict__ fg,
                              __nv_bfloat16* __restrict__ hi,
                              __nv_bfloat16* __restrict__ lo) {
    int i = blockIdx.x * blockDim.x + threadIdx.x;
    float4 h = ((const float4*)fh)[i];
    float4 g = ((const float4*)fg)[i];
    h.x *= g.x / (1.f + expf(-g.x));
    h.y *= g.y / (1.f + expf(-g.y));
    h.z *= g.z / (1.f + expf(-g.z));
    h.w *= g.w / (1.f + expf(-g.w));
    split4(h, hi, lo, (size_t)i * 4);
}

// ---------------------------------------------------------------------------
extern "C" void kernel_launch(void* const* d_in, const int* in_sizes, int n_in,
                              void* d_out, int out_size) {
    const int*   tokens       = (const int*)  d_in[0];
    const float* emb          = (const float*)d_in[1];
    const float* decay_norm_w = (const float*)d_in[2];
    const float* lambda_w     = (const float*)d_in[3];
    const float* quantity_w   = (const float*)d_in[4];
    const float* gate_w       = (const float*)d_in[5];
    const float* output_w     = (const float*)d_in[6];
    const float* ffn_norm_w   = (const float*)d_in[7];
    const float* w_h          = (const float*)d_in[8];
    const float* w_g          = (const float*)d_in[9];
    const float* w_o          = (const float*)d_in[10];
    const float* out_norm_w   = (const float*)d_in[11];
    float* out = (float*)d_out;

    float *X, *Q, *O, *G1, *FH, *FG, *NL;
    cudaGetSymbolAddress((void**)&X,  gX);
    cudaGetSymbolAddress((void**)&Q,  gQ);
    cudaGetSymbolAddress((void**)&O,  gO);
    cudaGetSymbolAddress((void**)&G1, gG1);
    cudaGetSymbolAddress((void**)&FH, gFH);
    cudaGetSymbolAddress((void**)&FG, gFG);
    cudaGetSymbolAddress((void**)&NL, gNL);
    __nv_bfloat16 *Whi, *Wlo, *Ahi, *Alo;
    cudaGetSymbolAddress((void**)&Whi, gWhi);
    cudaGetSymbolAddress((void**)&Wlo, gWlo);
    cudaGetSymbolAddress((void**)&Ahi, gAhi);
    cudaGetSymbolAddress((void**)&Alo, gAlo);

    static bool attr_set = false;
    if (!attr_set) {
        cudaFuncSetAttribute(gemm_mma<0, 64>, cudaFuncAttributeMaxDynamicSharedMemorySize, GSMEM64);
        cudaFuncSetAttribute(gemm_mma<1, 64>, cudaFuncAttributeMaxDynamicSharedMemorySize, GSMEM64);
        cudaFuncSetAttribute(gemm_mma<2, 64>, cudaFuncAttributeMaxDynamicSharedMemorySize, GSMEM64);
        cudaFuncSetAttribute(gemm_1p,         cudaFuncAttributeMaxDynamicSharedMemorySize, P_GSMEM);
        attr_set = true;
    }

    // ---- weight conversion (2 launches) ---------------------------------
    // emb -> fp16 single (stored in gWhi emb region, reinterpreted)
    cvt_f16_k<<<(int)(W_EMB_SZ / 4 + 255) / 256, 256>>>(emb, (__half*)Whi,
                                                        (int)(W_EMB_SZ / 4));
    wcvt_layers_k<<<(cL * L4 + 255) / 256, 256>>>(quantity_w, gate_w, output_w,
                                                  w_h, w_g, w_o, Whi, Wlo);

    const int EW_D = (cM * cD / 4) / 256;
    const int EW_H = (cM * cH / 4) / 256;

    embed_k<<<EW_D, 256>>>(tokens, emb, X);

    for (int l = 0; l < cL; l++) {
        size_t base = W_EMB_SZ + (size_t)l * W_LAYER_SZ;
        size_t oQG = base;                         // Q | G adjacent (1024 x 512)
        size_t oO  = base + 2 * (size_t)cD * cD;
        size_t oWHG = base + 3 * (size_t)cD * cD;  // WH | WG adjacent (4096 x 512)
        size_t oWO = oWHG + 2 * (size_t)cH * cD;

        rms_lambda_k<<<cM, 128>>>(X, decay_norm_w + (size_t)l * cD,
                                  lambda_w + (size_t)l * cD, Ahi, Alo, NL);
        // fused Q+gate projection, dual-output -> Q (cols 0..511), G1 (512..1023)
        gemm_mma<0, 64><<<dim3(1024 / 64, cM / 128), 256, GSMEM64>>>(
            Ahi, Alo, Whi + oQG, Wlo + oQG, Q, G1, cD, nullptr, cD, cD);
        attn_k<<<dim3(cD / 64, cS / 64, cB), 256>>>(Q, NL, O);
        silu_cvt_k<<<EW_D, 256>>>(O, Ahi, Alo);
        // O-projection with fused gated residual: X += (silu(O) @ Wo^T) * G1
        gemm_mma<2, 64><<<dim3(cD / 64, cM / 128), 256, GSMEM64>>>(
            Ahi, Alo, Whi + oO, Wlo + oO, X, nullptr, 0, G1, cD, cD);
        rms_cvt_k<<<cM, 128>>>(X, ffn_norm_w + (size_t)l * cD, Ahi, Alo);
        // fused FFN up+gate, dual-output -> FH, FG
        gemm_mma<0, 64><<<dim3(4096 / 64, cM / 128), 256, GSMEM64>>>(
            Ahi, Alo, Whi + oWHG, Wlo + oWHG, FH, FG, cH, nullptr, cH, cD);
        mulsilu_cvt_k<<<EW_H, 256>>>(FH, FG, Ahi, Alo);
        gemm_mma<1, 64><<<dim3(cD / 64, cM / 128), 256, GSMEM64>>>(
            Ahi, Alo, Whi + oWO, Wlo + oWO, X, nullptr, 0, nullptr, cD, cH);
    }

    // logits: fp16 1-product (A single fp16, emb single fp16)
    rms_cvt_f16s_k<<<cM, 128>>>(X, out_norm_w, (__half*)Ahi);
    gemm_1p<<<dim3(cV / 128, cM / 128), 256, P_GSMEM>>>(
        (__half*)Ahi, (__half*)Whi, out, cV, cD);
}

// round 14
// speedup vs baseline: 1.1015x; 1.0068x over previous
#include <cuda_runtime.h>
#include <cuda_bf16.h>
#include <cuda_fp16.h>
#include <cstdint>
#include <math.h>

// Problem constants
constexpr int cB = 2;
constexpr int cS = 2048;
constexpr int cD = 512;
constexpr int cH = 2048;
constexpr int cL = 4;
constexpr int cV = 32000;
constexpr int cM = cB * cS;  // 4096 rows

// ---------------- static device scratch (no allocation allowed) -------------
__device__ float gX [cM * cD];
__device__ float gQ [cM * cD];
__device__ float gG1[cM * cD];
__device__ float gFH[cM * cH];
__device__ float gFG[cM * cH];
__device__ float gNL[cM];

// 16-bit weight buffers. emb region of gWhi holds fp16 (logits path);
// layer regions hold bf16 hi (gWhi) / lo (gWlo).
constexpr size_t W_EMB_SZ   = (size_t)cV * cD;
constexpr size_t W_LAYER_SZ = 3 * (size_t)cD * cD + 3 * (size_t)cH * cD;
constexpr size_t W_TOTAL    = W_EMB_SZ + cL * W_LAYER_SZ;

__device__ __nv_bfloat16 gWhi[W_TOTAL];
__device__ __nv_bfloat16 gWlo[W_TOTAL];
__device__ __nv_bfloat16 gAhi[(size_t)cM * cH];
__device__ __nv_bfloat16 gAlo[(size_t)cM * cH];

// ============================ PTX helpers ===================================
__device__ __forceinline__ uint32_t smem_u32(const void* p) {
    uint32_t a;
    asm("{ .reg .u64 t; cvta.to.shared.u64 t, %1; cvt.u32.u64 %0, t; }"
        : "=r"(a) : "l"(p));
    return a;
}
__device__ __forceinline__ void cp16(uint32_t dst, const void* src) {
    asm volatile("cp.async.cg.shared.global [%0], [%1], 16;" :: "r"(dst), "l"(src));
}
#define CP_COMMIT() asm volatile("cp.async.commit_group;" ::: "memory")
#define CP_WAIT(n)  asm volatile("cp.async.wait_group %0;" :: "n"(n) : "memory")

__device__ __forceinline__ void ldsm4(uint32_t* r, uint32_t addr) {
    asm volatile("ldmatrix.sync.aligned.m8n8.x4.shared.b16 {%0,%1,%2,%3}, [%4];"
        : "=r"(r[0]), "=r"(r[1]), "=r"(r[2]), "=r"(r[3]) : "r"(addr));
}
__device__ __forceinline__ void mma16816(float* c, const uint32_t* a, const uint32_t* b) {
    asm volatile(
        "mma.sync.aligned.m16n8k16.row.col.f32.bf16.bf16.f32 "
        "{%0,%1,%2,%3}, {%4,%5,%6,%7}, {%8,%9}, {%0,%1,%2,%3};"
        : "+f"(c[0]), "+f"(c[1]), "+f"(c[2]), "+f"(c[3])
        : "r"(a[0]), "r"(a[1]), "r"(a[2]), "r"(a[3]), "r"(b[0]), "r"(b[1]));
}
__device__ __forceinline__ void mma16816h(float* c, const uint32_t* a, const uint32_t* b) {
    asm volatile(
        "mma.sync.aligned.m16n8k16.row.col.f32.f16.f16.f32 "
        "{%0,%1,%2,%3}, {%4,%5,%6,%7}, {%8,%9}, {%0,%1,%2,%3};"
        : "+f"(c[0]), "+f"(c[1]), "+f"(c[2]), "+f"(c[3])
        : "r"(a[0]), "r"(a[1]), "r"(a[2]), "r"(a[3]), "r"(b[0]), "r"(b[1]));
}

// hi/lo split of 4 floats -> packed bf16x2 writes
__device__ __forceinline__ void split4(float4 v, __nv_bfloat16* hi, __nv_bfloat16* lo,
                                       size_t eoff) {
    __nv_bfloat16 hx = __float2bfloat16_rn(v.x);
    __nv_bfloat16 hy = __float2bfloat16_rn(v.y);
    __nv_bfloat16 hz = __float2bfloat16_rn(v.z);
    __nv_bfloat16 hw = __float2bfloat16_rn(v.w);
    __nv_bfloat16 lx = __float2bfloat16_rn(v.x - __bfloat162float(hx));
    __nv_bfloat16 ly = __float2bfloat16_rn(v.y - __bfloat162float(hy));
    __nv_bfloat16 lz = __float2bfloat16_rn(v.z - __bfloat162float(hz));
    __nv_bfloat16 lw = __float2bfloat16_rn(v.w - __bfloat162float(hw));
    __nv_bfloat162* H = (__nv_bfloat162*)(hi + eoff);
    __nv_bfloat162* L = (__nv_bfloat16* )(lo + eoff) ? (__nv_bfloat162*)(lo + eoff) : nullptr;
    H[0] = __nv_bfloat162(hx, hy); H[1] = __nv_bfloat162(hz, hw);
    L[0] = __nv_bfloat162(lx, ly); L[1] = __nv_bfloat162(lz, lw);
}

// ---------------------------------------------------------------------------
// Weight conversion: emb -> single fp16 (logits operand)
__global__ void cvt_f16_k(const float* __restrict__ s,
                          __half* __restrict__ h, int n4) {
    int i = blockIdx.x * blockDim.x + threadIdx.x;
    if (i >= n4) return;
    float4 v = ((const float4*)s)[i];
    __half2* H = (__half2*)(h + (size_t)i * 4);
    H[0] = __halves2half2(__float2half_rn(v.x), __float2half_rn(v.y));
    H[1] = __halves2half2(__float2half_rn(v.z), __float2half_rn(v.w));
}

// All-layer weight conversion in one launch (f4-index space per layer)
constexpr int L4 = 983040;
__global__ void wcvt_layers_k(const float* __restrict__ q, const float* __restrict__ g,
                              const float* __restrict__ o, const float* __restrict__ wh,
                              const float* __restrict__ wg, const float* __restrict__ wo,
                              __nv_bfloat16* __restrict__ hi, __nv_bfloat16* __restrict__ lo) {
    int idx = blockIdx.x * blockDim.x + threadIdx.x;
    if (idx >= cL * L4) return;
    int l = idx / L4;
    int r = idx - l * L4;
    const float* src;
    size_t dst = W_EMB_SZ + (size_t)l * W_LAYER_SZ + (size_t)r * 4;
    if (r < 196608) {
        int t = r / 65536, rr = r - t * 65536;
        const float* bases[3] = {q, g, o};
        src = bases[t] + (size_t)l * 262144 + (size_t)rr * 4;
    } else if (r < 458752) {
        src = wh + (size_t)l * 1048576 + (size_t)(r - 196608) * 4;
    } else if (r < 720896) {
        src = wg + (size_t)l * 1048576 + (size_t)(r - 458752) * 4;
    } else {
        src = wo + (size_t)l * 1048576 + (size_t)(r - 720896) * 4;
    }
    split4(*(const float4*)src, hi, lo, dst);
}

// ---------------------------------------------------------------------------
// bf16x3 mma.sync NT GEMM (layer GEMMs). CTA tile 128 x BN=64, 8 warps,
// K-chunk 32, cp.async double buffer, one barrier per chunk.
// EPI: 0 = store (dual-output: C2/nSplit select buffer by n0),
//      1 = C += acc, 2 = C += acc * gate (gate row stride = Ndim).
constexpr int PAD = 40;

template<int BN>
__device__ __forceinline__ void stage_chunk(
    const __nv_bfloat16* __restrict__ Ahi, const __nv_bfloat16* __restrict__ Alo,
    const __nv_bfloat16* __restrict__ Bhi, const __nv_bfloat16* __restrict__ Blo,
    int m0, int n0, int Kdim, int kt, uint32_t sbuf, int tid) {
    constexpr int OFF_ALO = 128 * PAD;
    constexpr int OFF_BHI = 256 * PAD;
    constexpr int OFF_BLO = (256 + BN) * PAD;
    #pragma unroll
    for (int it = 0; it < 2; it++) {
        int i = tid + it * 256;
        int r = i >> 2, c = (i & 3) << 3;
        size_t ga = (size_t)(m0 + r) * Kdim + kt + c;
        uint32_t d = sbuf + (uint32_t)(r * PAD + c) * 2;
        cp16(d, Ahi + ga);
        cp16(d + OFF_ALO * 2, Alo + ga);
    }
    #pragma unroll
    for (int it = 0; it < BN / 64; it++) {
        int i = tid + it * 256;
        int r = i >> 2, c = (i & 3) << 3;
        size_t gb = (size_t)(n0 + r) * Kdim + kt + c;
        uint32_t d = sbuf + (uint32_t)(r * PAD + c) * 2;
        cp16(d + OFF_BHI * 2, Bhi + gb);
        cp16(d + OFF_BLO * 2, Blo + gb);
    }
}

template<int EPI, int BN>
__global__ void __launch_bounds__(256) gemm_mma(
    const __nv_bfloat16* __restrict__ Ahi, const __nv_bfloat16* __restrict__ Alo,
    const __nv_bfloat16* __restrict__ Bhi, const __nv_bfloat16* __restrict__ Blo,
    float* __restrict__ C, float* __restrict__ C2, int nSplit,
    const float* __restrict__ gate, int Ndim, int Kdim) {
    constexpr int WNT = BN / 2;
    constexpr int NT  = WNT / 8;
    constexpr int NP  = WNT / 16;
    constexpr int OFF_ALO = 128 * PAD;
    constexpr int OFF_BHI = 256 * PAD;
    constexpr int OFF_BLO = (256 + BN) * PAD;
    constexpr int BUF_BYTES = (256 + 2 * BN) * PAD * 2;

    extern __shared__ char smc[];
    const uint32_t sbase = smem_u32(smc);
    const int tid = threadIdx.x;
    const int lane = tid & 31, wid = tid >> 5;
    const int wm = wid & 3, wn = wid >> 2;
    const int m0 = blockIdx.y * 128, n0 = blockIdx.x * BN;
    const int NC = Kdim >> 5;

    float acc[2][NT][4] = {};

    const uint32_t a_lane = (uint32_t)((lane & 15) * PAD + ((lane >> 4) << 3)) * 2;
    const uint32_t b_lane = (uint32_t)(((lane & 7) + ((lane >> 4) << 3)) * PAD
                                       + (((lane >> 3) & 1) << 3)) * 2;

    stage_chunk<BN>(Ahi, Alo, Bhi, Blo, m0, n0, Kdim, 0, sbase, tid);
    CP_COMMIT();

    for (int c = 0; c < NC; c++) {
        const int buf = c & 1;
        CP_WAIT(0);          // chunk c resident in smem
        __syncthreads();     // all warps done with compute(c-1); chunk c visible
        if (c + 1 < NC) {
            stage_chunk<BN>(Ahi, Alo, Bhi, Blo, m0, n0, Kdim, (c + 1) << 5,
                            sbase + (buf ^ 1) * BUF_BYTES, tid);
            CP_COMMIT();
        }

        const uint32_t sb = sbase + buf * BUF_BYTES;
        #pragma unroll
        for (int ks = 0; ks < 32; ks += 16) {
            uint32_t ah[2][4], al[2][4], bh[NP][4], bl[NP][4];
            #pragma unroll
            for (int mt = 0; mt < 2; mt++) {
                uint32_t ar = sb + (uint32_t)(((wm * 32 + mt * 16) * PAD + ks) * 2) + a_lane;
                ldsm4(ah[mt], ar);
                ldsm4(al[mt], ar + OFF_ALO * 2);
            }
            #pragma unroll
            for (int p = 0; p < NP; p++) {
                uint32_t br = sb + (uint32_t)(((wn * WNT + p * 16) * PAD + ks) * 2) + b_lane;
                ldsm4(bh[p], br + OFF_BHI * 2);
                ldsm4(bl[p], br + OFF_BLO * 2);
            }
            #pragma unroll
            for (int mt = 0; mt < 2; mt++)
                #pragma unroll
                for (int j = 0; j < NT; j++) {
                    const uint32_t* bhp = &bh[j >> 1][(j & 1) * 2];
                    const uint32_t* blp = &bl[j >> 1][(j & 1) * 2];
                    mma16816(acc[mt][j], ah[mt], bhp);
                    mma16816(acc[mt][j], ah[mt], blp);
                    mma16816(acc[mt][j], al[mt], bhp);
                }
        }
    }

    // dual-output select (uniform per CTA; BN=64 never straddles nSplit)
    float* Cout = C;
    int nbase = n0;
    if (EPI == 0 && C2 != nullptr && n0 >= nSplit) { Cout = C2; nbase = n0 - nSplit; }

    #pragma unroll
    for (int mt = 0; mt < 2; mt++) {
        int row = m0 + wm * 32 + mt * 16 + (lane >> 2);
        #pragma unroll
        for (int j = 0; j < NT; j++) {
            int col = nbase + wn * WNT + j * 8 + (lane & 3) * 2;
            float* c0 = Cout + (size_t)row * Ndim + col;
            float* c1 = Cout + (size_t)(row + 8) * Ndim + col;
            if (EPI == 1) {
                c0[0] += acc[mt][j][0]; c0[1] += acc[mt][j][1];
                c1[0] += acc[mt][j][2]; c1[1] += acc[mt][j][3];
            } else if (EPI == 2) {
                const float* g0 = gate + (size_t)row * Ndim + col;
                const float* g1 = gate + (size_t)(row + 8) * Ndim + col;
                c0[0] += acc[mt][j][0] * g0[0]; c0[1] += acc[mt][j][1] * g0[1];
                c1[0] += acc[mt][j][2] * g1[0]; c1[1] += acc[mt][j][3] * g1[1];
            } else {
                *(float2*)c0 = make_float2(acc[mt][j][0], acc[mt][j][1]);
                *(float2*)c1 = make_float2(acc[mt][j][2], acc[mt][j][3]);
            }
        }
    }
}

constexpr int GSMEM64 = 2 * (256 + 128) * PAD * 2;   // 61440

// ---------------------------------------------------------------------------
// fp16 1-product logits GEMM: C = A @ B^T, both single-rounded fp16.
// CTA tile 128 x 128, 8 warps (warp 32x64), K-chunk 32, double buffer,
// one barrier per chunk.
constexpr int P_OFF_B   = 128 * PAD;
constexpr int P_BUF_BYTES = (128 + 128) * PAD * 2;   // 20480
constexpr int P_GSMEM = 2 * P_BUF_BYTES;             // 40960

__device__ __forceinline__ void stage_1p(
    const __half* __restrict__ Ah, const __half* __restrict__ Bh,
    int m0, int n0, int Kdim, int kt, uint32_t sbuf, int tid) {
    #pragma unroll
    for (int it = 0; it < 2; it++) {
        int i = tid + it * 256;
        int r = i >> 2, c = (i & 3) << 3;
        size_t ga = (size_t)(m0 + r) * Kdim + kt + c;
        cp16(sbuf + (uint32_t)(r * PAD + c) * 2, Ah + ga);
    }
    #pragma unroll
    for (int it = 0; it < 2; it++) {
        int i = tid + it * 256;
        int r = i >> 2, c = (i & 3) << 3;
        size_t gb = (size_t)(n0 + r) * Kdim + kt + c;
        cp16(sbuf + P_OFF_B * 2 + (uint32_t)(r * PAD + c) * 2, Bh + gb);
    }
}

__global__ void __launch_bounds__(256) gemm_1p(
    const __half* __restrict__ Ah, const __half* __restrict__ Bh,
    float* __restrict__ C, int Ndim, int Kdim) {
    extern __shared__ char smc[];
    const uint32_t sbase = smem_u32(smc);
    const int tid = threadIdx.x;
    const int lane = tid & 31, wid = tid >> 5;
    const int wm = wid & 3, wn = wid >> 2;
    const int m0 = blockIdx.y * 128, n0 = blockIdx.x * 128;
    const int NC = Kdim >> 5;

    float acc[2][8][4] = {};

    const uint32_t a_lane = (uint32_t)((lane & 15) * PAD + ((lane >> 4) << 3)) * 2;
    const uint32_t b_lane = (uint32_t)(((lane & 7) + ((lane >> 4) << 3)) * PAD
                                       + (((lane >> 3) & 1) << 3)) * 2;

    stage_1p(Ah, Bh, m0, n0, Kdim, 0, sbase, tid);
    CP_COMMIT();

    for (int c = 0; c < NC; c++) {
        const int buf = c & 1;
        CP_WAIT(0);
        __syncthreads();
        if (c + 1 < NC) {
            stage_1p(Ah, Bh, m0, n0, Kdim, (c + 1) << 5,
                     sbase + (buf ^ 1) * P_BUF_BYTES, tid);
            CP_COMMIT();
        }

        const uint32_t sb = sbase + buf * P_BUF_BYTES;
        #pragma unroll
        for (int ks = 0; ks < 32; ks += 16) {
            uint32_t ah[2][4], bw[4][4];
            #pragma unroll
            for (int mt = 0; mt < 2; mt++) {
                uint32_t ar = sb + (uint32_t)(((wm * 32 + mt * 16) * PAD + ks) * 2) + a_lane;
                ldsm4(ah[mt], ar);
            }
            #pragma unroll
            for (int p = 0; p < 4; p++) {
                uint32_t br = sb + (uint32_t)(((wn * 64 + p * 16) * PAD + ks) * 2) + b_lane;
                ldsm4(bw[p], br + P_OFF_B * 2);
            }
            #pragma unroll
            for (int mt = 0; mt < 2; mt++)
                #pragma unroll
                for (int j = 0; j < 8; j++) {
                    const uint32_t* bp = &bw[j >> 1][(j & 1) * 2];
                    mma16816h(acc[mt][j], ah[mt], bp);
                }
        }
    }

    #pragma unroll
    for (int mt = 0; mt < 2; mt++) {
        int row = m0 + wm * 32 + mt * 16 + (lane >> 2);
        #pragma unroll
        for (int j = 0; j < 8; j++) {
            int col = n0 + wn * 64 + j * 8 + (lane & 3) * 2;
            *(float2*)(C + (size_t)row * Ndim + col) =
                make_float2(acc[mt][j][0], acc[mt][j][1]);
            *(float2*)(C + (size_t)(row + 8) * Ndim + col) =
                make_float2(acc[mt][j][2], acc[mt][j][3]);
        }
    }
}

// ---------------------------------------------------------------------------
// Embedding gather
__global__ void embed_k(const int* __restrict__ tok,
                        const float* __restrict__ emb,
                        float* __restrict__ x) {
    int i = blockIdx.x * blockDim.x + threadIdx.x;
    int row = i / (cD / 4);
    int c   = i % (cD / 4);
    int t = tok[row];
    ((float4*)x)[i] = ((const float4*)(emb + (size_t)t * cD))[c];
}

// RMSNorm + lambda fused: h = rmsnorm(x)*w -> (hi,lo) bf16; nl = logsigmoid(h.lw)
__global__ void rms_lambda_k(const float* __restrict__ x,
                             const float* __restrict__ w,
                             const float* __restrict__ lw,
                             __nv_bfloat16* __restrict__ hi,
                             __nv_bfloat16* __restrict__ lo,
                             float* __restrict__ nlout) {
    int row = blockIdx.x;
    int tid = threadIdx.x;
    float4 v = ((const float4*)(x + (size_t)row * cD))[tid];
    float ss = v.x * v.x + v.y * v.y + v.z * v.z + v.w * v.w;
    #pragma unroll
    for (int o = 16; o; o >>= 1) ss += __shfl_xor_sync(0xFFFFFFFFu, ss, o);
    __shared__ float sred[4];
    if ((tid & 31) == 0) sred[tid >> 5] = ss;
    __syncthreads();
    float sc = rsqrtf((sred[0] + sred[1] + sred[2] + sred[3]) * (1.0f / cD) + 1e-6f);
    float4 wv = ((const float4*)w)[tid];
    float4 h;
    h.x = v.x * sc * wv.x; h.y = v.y * sc * wv.y;
    h.z = v.z * sc * wv.z; h.w = v.w * sc * wv.w;
    split4(h, hi, lo, (size_t)row * cD + tid * 4);
    float4 lv = ((const float4*)lw)[tid];
    float d = h.x * lv.x + h.y * lv.y + h.z * lv.z + h.w * lv.w;
    #pragma unroll
    for (int o = 16; o; o >>= 1) d += __shfl_xor_sync(0xFFFFFFFFu, d, o);
    __shared__ float dred[4];
    if ((tid & 31) == 0) dred[tid >> 5] = d;
    __syncthreads();
    if (tid == 0) {
        float z = dred[0] + dred[1] + dred[2] + dred[3];
        nlout[row] = (z >= 0.f) ? -log1pf(expf(-z)) : (z - log1pf(expf(z)));
    }
}

// RMSNorm -> bf16 (hi,lo)
__global__ void rms_cvt_k(const float* __restrict__ x,
                          const float* __restrict__ w,
                          __nv_bfloat16* __restrict__ hi,
                          __nv_bfloat16* __restrict__ lo) {
    int row = blockIdx.x;
    int tid = threadIdx.x;
    float4 v = ((const float4*)(x + (size_t)row * cD))[tid];
    float ss = v.x * v.x + v.y * v.y + v.z * v.z + v.w * v.w;
    #pragma unroll
    for (int o = 16; o; o >>= 1) ss += __shfl_xor_sync(0xFFFFFFFFu, ss, o);
    __shared__ float sred[4];
    if ((tid & 31) == 0) sred[tid >> 5] = ss;
    __syncthreads();
    float sc = rsqrtf((sred[0] + sred[1] + sred[2] + sred[3]) * (1.0f / cD) + 1e-6f);
    float4 wv = ((const float4*)w)[tid];
    float4 h;
    h.x = v.x * sc * wv.x; h.y = v.y * sc * wv.y;
    h.z = v.z * sc * wv.z; h.w = v.w * sc * wv.w;
    split4(h, hi, lo, (size_t)row * cD + tid * 4);
}

// RMSNorm -> single fp16 (logits activation)
__global__ void rms_cvt_f16s_k(const float* __restrict__ x,
                               const float* __restrict__ w,
                               __half* __restrict__ h16) {
    int row = blockIdx.x;
    int tid = threadIdx.x;
    float4 v = ((const float4*)(x + (size_t)row * cD))[tid];
    float ss = v.x * v.x + v.y * v.y + v.z * v.z + v.w * v.w;
    #pragma unroll
    for (int o = 16; o; o >>= 1) ss += __shfl_xor_sync(0xFFFFFFFFu, ss, o);
    __shared__ float sred[4];
    if ((tid & 31) == 0) sred[tid >> 5] = ss;
    __syncthreads();
    float sc = rsqrtf((sred[0] + sred[1] + sred[2] + sred[3]) * (1.0f / cD) + 1e-6f);
    float4 wv = ((const float4*)w)[tid];
    __half2* H = (__half2*)(h16 + (size_t)row * cD + tid * 4);
    H[0] = __halves2half2(__float2half_rn(v.x * sc * wv.x),
                          __float2half_rn(v.y * sc * wv.y));
    H[1] = __halves2half2(__float2half_rn(v.z * sc * wv.z),
                          __float2half_rn(v.w * sc * wv.w));
}

// Windowed decay attention with one-shot liveness scan.
// Fused epilogue: out = silu(attn_out) -> bf16 (hi,lo) written to Ahi/Alo.
__global__ void __launch_bounds__(256) attn_k(const float* __restrict__ Q,
                                              const float* __restrict__ NL,
                                              __nv_bfloat16* __restrict__ hi,
                                              __nv_bfloat16* __restrict__ lo) {
    __shared__ float q_sm[16][64];
    __shared__ float w_sm[16][64];
    __shared__ float nl_sm[16];
    __shared__ int minLive;

    int b  = blockIdx.z;
    int s0 = blockIdx.y * 64;
    int d0 = blockIdx.x * 64;
    int tid = threadIdx.x;
    int tx = tid & 15;
    int ty = tid >> 4;

    float acc[4][4] = {};
    const float* Qb  = Q  + (size_t)b * cS * cD;
    const float* NLb = NL + (size_t)b * cS;

    int t_lo = s0 - 1024; if (t_lo < 0) t_lo = 0;
    int t_hi = s0 + 63;
    int n_tiles = (t_hi - t_lo + 16) >> 4;

    if (tid == 0) minLive = n_tiles - 1;
    __syncthreads();
    if (tid < n_tiles) {
        int t0 = t_lo + tid * 16;
        int live;
        if (t0 + 15 >= s0) {
            live = 1;
        } else {
            float mx = -1e30f;
            #pragma unroll 4
            for (int k = 0; k < 16; k++) mx = fmaxf(mx, NLb[t0 + k]);
            live = (mx * (float)(s0 - (t0 + 15)) > -27.6f);
        }
        if (live) atomicMin(&minLive, tid);
    }
    __syncthreads();
    int t_start = t_lo + minLive * 16;

    for (int t0 = t_start; t0 <= t_hi; t0 += 16) {
        if (tid < 16) {
            int t = t0 + tid;
            nl_sm[tid] = NLb[t < cS ? t : (cS - 1)];
        }
        {
            int k  = tid >> 4;
            int dc = (tid & 15) << 2;
            int t = t0 + k; if (t > cS - 1) t = cS - 1;
            float4 qv = *(const float4*)(Qb + (size_t)t * cD + d0 + dc);
            *(float4*)&q_sm[k][dc] = qv;
        }
        __syncthreads();
        #pragma unroll
        for (int j = 0; j < 4; j++) {
            int idx = tid + j * 256;
            int k  = idx >> 6;
            int sl = idx & 63;
            int t = t0 + k, s = s0 + sl;
            float w = 0.f;
            if (t <= s) w = __expf(nl_sm[k] * (float)(s - t));
            w_sm[k][sl] = w;
        }
        __syncthreads();

        #pragma unroll
        for (int k = 0; k < 16; k++) {
            float4 qv = *(const float4*)&q_sm[k][tx * 4];
            float wv0 = w_sm[k][ty * 4 + 0];
            float wv1 = w_sm[k][ty * 4 + 1];
            float wv2 = w_sm[k][ty * 4 + 2];
            float wv3 = w_sm[k][ty * 4 + 3];
            acc[0][0] += wv0 * qv.x; acc[0][1] += wv0 * qv.y; acc[0][2] += wv0 * qv.z; acc[0][3] += wv0 * qv.w;
            acc[1][0] += wv1 * qv.x; acc[1][1] += wv1 * qv.y; acc[1][2] += wv1 * qv.z; acc[1][3] += wv1 * qv.w;
            acc[2][0] += wv2 * qv.x; acc[2][1] += wv2 * qv.y; acc[2][2] += wv2 * qv.z; acc[2][3] += wv2 * qv.w;
            acc[3][0] += wv3 * qv.x; acc[3][1] += wv3 * qv.y; acc[3][2] += wv3 * qv.z; acc[3][3] += wv3 * qv.w;
        }
        __syncthreads();
    }

    #pragma unroll
    for (int i = 0; i < 4; i++) {
        float4 o4;
        o4.x = acc[i][0] / (1.f + expf(-acc[i][0]));
        o4.y = acc[i][1] / (1.f + expf(-acc[i][1]));
        o4.z = acc[i][2] / (1.f + expf(-acc[i][2]));
        o4.w = acc[i][3] / (1.f + expf(-acc[i][3]));
        split4(o4, hi, lo,
               (size_t)(b * cS + s0 + ty * 4 + i) * cD + d0 + tx * 4);
    }
}

// fh * silu(fg) -> bf16 (hi, lo)
__global__ void mulsilu_cvt_k(const float* __restrict__ fh,
                              const float* __restrict__ fg,
                              __nv_bfloat16* __restrict__ hi,
                              __nv_bfloat16* __restrict__ lo) {
    int i = blockIdx.x * blockDim.x + threadIdx.x;
    float4 h = ((const float4*)fh)[i];
    float4 g = ((const float4*)fg)[i];
    h.x *= g.x / (1.f + expf(-g.x));
    h.y *= g.y / (1.f + expf(-g.y));
    h.z *= g.z / (1.f + expf(-g.z));
    h.w *= g.w / (1.f + expf(-g.w));
    split4(h, hi, lo, (size_t)i * 4);
}

// ---------------------------------------------------------------------------
extern "C" void kernel_launch(void* const* d_in, const int* in_sizes, int n_in,
                              void* d_out, int out_size) {
    const int*   tokens       = (const int*)  d_in[0];
    const float* emb          = (const float*)d_in[1];
    const float* decay_norm_w = (const float*)d_in[2];
    const float* lambda_w     = (const float*)d_in[3];
    const float* quantity_w   = (const float*)d_in[4];
    const float* gate_w       = (const float*)d_in[5];
    const float* output_w     = (const float*)d_in[6];
    const float* ffn_norm_w   = (const float*)d_in[7];
    const float* w_h          = (const float*)d_in[8];
    const float* w_g          = (const float*)d_in[9];
    const float* w_o          = (const float*)d_in[10];
    const float* out_norm_w   = (const float*)d_in[11];
    float* out = (float*)d_out;

    float *X, *Q, *G1, *FH, *FG, *NL;
    cudaGetSymbolAddress((void**)&X,  gX);
    cudaGetSymbolAddress((void**)&Q,  gQ);
    cudaGetSymbolAddress((void**)&G1, gG1);
    cudaGetSymbolAddress((void**)&FH, gFH);
    cudaGetSymbolAddress((void**)&FG, gFG);
    cudaGetSymbolAddress((void**)&NL, gNL);
    __nv_bfloat16 *Whi, *Wlo, *Ahi, *Alo;
    cudaGetSymbolAddress((void**)&Whi, gWhi);
    cudaGetSymbolAddress((void**)&Wlo, gWlo);
    cudaGetSymbolAddress((void**)&Ahi, gAhi);
    cudaGetSymbolAddress((void**)&Alo, gAlo);

    static bool attr_set = false;
    if (!attr_set) {
        cudaFuncSetAttribute(gemm_mma<0, 64>, cudaFuncAttributeMaxDynamicSharedMemorySize, GSMEM64);
        cudaFuncSetAttribute(gemm_mma<1, 64>, cudaFuncAttributeMaxDynamicSharedMemorySize, GSMEM64);
        cudaFuncSetAttribute(gemm_mma<2, 64>, cudaFuncAttributeMaxDynamicSharedMemorySize, GSMEM64);
        cudaFuncSetAttribute(gemm_1p,         cudaFuncAttributeMaxDynamicSharedMemorySize, P_GSMEM);
        attr_set = true;
    }

    // ---- weight conversion (2 launches) ---------------------------------
    // emb -> fp16 single (stored in gWhi emb region, reinterpreted)
    cvt_f16_k<<<(int)(W_EMB_SZ / 4 + 255) / 256, 256>>>(emb, (__half*)Whi,
                                                        (int)(W_EMB_SZ / 4));
    wcvt_layers_k<<<(cL * L4 + 255) / 256, 256>>>(quantity_w, gate_w, output_w,
                                                  w_h, w_g, w_o, Whi, Wlo);

    const int EW_D = (cM * cD / 4) / 256;
    const int EW_H = (cM * cH / 4) / 256;

    embed_k<<<EW_D, 256>>>(tokens, emb, X);

    for (int l = 0; l < cL; l++) {
        size_t base = W_EMB_SZ + (size_t)l * W_LAYER_SZ;
        size_t oQG = base;                         // Q | G adjacent (1024 x 512)
        size_t oO  = base + 2 * (size_t)cD * cD;
        size_t oWHG = base + 3 * (size_t)cD * cD;  // WH | WG adjacent (4096 x 512)
        size_t oWO = oWHG + 2 * (size_t)cH * cD;

        rms_lambda_k<<<cM, 128>>>(X, decay_norm_w + (size_t)l * cD,
                                  lambda_w + (size_t)l * cD, Ahi, Alo, NL);
        // fused Q+gate projection, dual-output -> Q (cols 0..511), G1 (512..1023)
        gemm_mma<0, 64><<<dim3(1024 / 64, cM / 128), 256, GSMEM64>>>(
            Ahi, Alo, Whi + oQG, Wlo + oQG, Q, G1, cD, nullptr, cD, cD);
        // attention with fused silu+split epilogue -> Ahi/Alo directly
        attn_k<<<dim3(cD / 64, cS / 64, cB), 256>>>(Q, NL, Ahi, Alo);
        // O-projection with fused gated residual: X += (silu(O) @ Wo^T) * G1
        gemm_mma<2, 64><<<dim3(cD / 64, cM / 128), 256, GSMEM64>>>(
            Ahi, Alo, Whi + oO, Wlo + oO, X, nullptr, 0, G1, cD, cD);
        rms_cvt_k<<<cM, 128>>>(X, ffn_norm_w + (size_t)l * cD, Ahi, Alo);
        // fused FFN up+gate, dual-output -> FH, FG
        gemm_mma<0, 64><<<dim3(4096 / 64, cM / 128), 256, GSMEM64>>>(
            Ahi, Alo, Whi + oWHG, Wlo + oWHG, FH, FG, cH, nullptr, cH, cD);
        mulsilu_cvt_k<<<EW_H, 256>>>(FH, FG, Ahi, Alo);
        gemm_mma<1, 64><<<dim3(cD / 64, cM / 128), 256, GSMEM64>>>(
            Ahi, Alo, Whi + oWO, Wlo + oWO, X, nullptr, 0, nullptr, cD, cH);
    }

    // logits: fp16 1-product (A single fp16, emb single fp16)
    rms_cvt_f16s_k<<<cM, 128>>>(X, out_norm_w, (__half*)Ahi);
    gemm_1p<<<dim3(cV / 128, cM / 128), 256, P_GSMEM>>>(
        (__half*)Ahi, (__half*)Whi, out, cV, cD);
}

// round 15
// speedup vs baseline: 1.1024x; 1.0009x over previous
#include <cuda_runtime.h>
#include <cuda_bf16.h>
#include <cuda_fp16.h>
#include <cstdint>
#include <math.h>

// Problem constants
constexpr int cB = 2;
constexpr int cS = 2048;
constexpr int cD = 512;
constexpr int cH = 2048;
constexpr int cL = 4;
constexpr int cV = 32000;
constexpr int cM = cB * cS;  // 4096 rows

// ---------------- static device scratch (no allocation allowed) -------------
__device__ float gX [cM * cD];
__device__ float gQ [cM * cD];
__device__ float gG1[cM * cD];
__device__ float gFH[cM * cH];
__device__ float gFG[cM * cH];
__device__ float gNL[cM];

// 16-bit weight buffers. emb region of gWhi holds fp16 (logits path);
// layer regions hold bf16 hi (gWhi) / lo (gWlo).
constexpr size_t W_EMB_SZ   = (size_t)cV * cD;
constexpr size_t W_LAYER_SZ = 3 * (size_t)cD * cD + 3 * (size_t)cH * cD;
constexpr size_t W_TOTAL    = W_EMB_SZ + cL * W_LAYER_SZ;

__device__ __nv_bfloat16 gWhi[W_TOTAL];
__device__ __nv_bfloat16 gWlo[W_TOTAL];
__device__ __nv_bfloat16 gAhi[(size_t)cM * cH];
__device__ __nv_bfloat16 gAlo[(size_t)cM * cH];

// ============================ PTX helpers ===================================
__device__ __forceinline__ uint32_t smem_u32(const void* p) {
    uint32_t a;
    asm("{ .reg .u64 t; cvta.to.shared.u64 t, %1; cvt.u32.u64 %0, t; }"
        : "=r"(a) : "l"(p));
    return a;
}
__device__ __forceinline__ void cp16(uint32_t dst, const void* src) {
    asm volatile("cp.async.cg.shared.global [%0], [%1], 16;" :: "r"(dst), "l"(src));
}
#define CP_COMMIT() asm volatile("cp.async.commit_group;" ::: "memory")
#define CP_WAIT(n)  asm volatile("cp.async.wait_group %0;" :: "n"(n) : "memory")

__device__ __forceinline__ void ldsm4(uint32_t* r, uint32_t addr) {
    asm volatile("ldmatrix.sync.aligned.m8n8.x4.shared.b16 {%0,%1,%2,%3}, [%4];"
        : "=r"(r[0]), "=r"(r[1]), "=r"(r[2]), "=r"(r[3]) : "r"(addr));
}
__device__ __forceinline__ void mma16816(float* c, const uint32_t* a, const uint32_t* b) {
    asm volatile(
        "mma.sync.aligned.m16n8k16.row.col.f32.bf16.bf16.f32 "
        "{%0,%1,%2,%3}, {%4,%5,%6,%7}, {%8,%9}, {%0,%1,%2,%3};"
        : "+f"(c[0]), "+f"(c[1]), "+f"(c[2]), "+f"(c[3])
        : "r"(a[0]), "r"(a[1]), "r"(a[2]), "r"(a[3]), "r"(b[0]), "r"(b[1]));
}
__device__ __forceinline__ void mma16816h(float* c, const uint32_t* a, const uint32_t* b) {
    asm volatile(
        "mma.sync.aligned.m16n8k16.row.col.f32.f16.f16.f32 "
        "{%0,%1,%2,%3}, {%4,%5,%6,%7}, {%8,%9}, {%0,%1,%2,%3};"
        : "+f"(c[0]), "+f"(c[1]), "+f"(c[2]), "+f"(c[3])
        : "r"(a[0]), "r"(a[1]), "r"(a[2]), "r"(a[3]), "r"(b[0]), "r"(b[1]));
}

// hi/lo split of 4 floats -> packed bf16x2 writes
__device__ __forceinline__ void split4(float4 v, __nv_bfloat16* hi, __nv_bfloat16* lo,
                                       size_t eoff) {
    __nv_bfloat16 hx = __float2bfloat16_rn(v.x);
    __nv_bfloat16 hy = __float2bfloat16_rn(v.y);
    __nv_bfloat16 hz = __float2bfloat16_rn(v.z);
    __nv_bfloat16 hw = __float2bfloat16_rn(v.w);
    __nv_bfloat16 lx = __float2bfloat16_rn(v.x - __bfloat162float(hx));
    __nv_bfloat16 ly = __float2bfloat16_rn(v.y - __bfloat162float(hy));
    __nv_bfloat16 lz = __float2bfloat16_rn(v.z - __bfloat162float(hz));
    __nv_bfloat16 lw = __float2bfloat16_rn(v.w - __bfloat162float(hw));
    __nv_bfloat162* H = (__nv_bfloat162*)(hi + eoff);
    __nv_bfloat162* L = (__nv_bfloat16* )(lo + eoff) ? (__nv_bfloat162*)(lo + eoff) : nullptr;
    H[0] = __nv_bfloat162(hx, hy); H[1] = __nv_bfloat162(hz, hw);
    L[0] = __nv_bfloat162(lx, ly); L[1] = __nv_bfloat162(lz, lw);
}

// ---------------------------------------------------------------------------
// Weight conversion: emb -> single fp16 (logits operand)
__global__ void cvt_f16_k(const float* __restrict__ s,
                          __half* __restrict__ h, int n4) {
    int i = blockIdx.x * blockDim.x + threadIdx.x;
    if (i >= n4) return;
    float4 v = ((const float4*)s)[i];
    __half2* H = (__half2*)(h + (size_t)i * 4);
    H[0] = __halves2half2(__float2half_rn(v.x), __float2half_rn(v.y));
    H[1] = __halves2half2(__float2half_rn(v.z), __float2half_rn(v.w));
}

// All-layer weight conversion in one launch (f4-index space per layer)
constexpr int L4 = 983040;
__global__ void wcvt_layers_k(const float* __restrict__ q, const float* __restrict__ g,
                              const float* __restrict__ o, const float* __restrict__ wh,
                              const float* __restrict__ wg, const float* __restrict__ wo,
                              __nv_bfloat16* __restrict__ hi, __nv_bfloat16* __restrict__ lo) {
    int idx = blockIdx.x * blockDim.x + threadIdx.x;
    if (idx >= cL * L4) return;
    int l = idx / L4;
    int r = idx - l * L4;
    const float* src;
    size_t dst = W_EMB_SZ + (size_t)l * W_LAYER_SZ + (size_t)r * 4;
    if (r < 196608) {
        int t = r / 65536, rr = r - t * 65536;
        const float* bases[3] = {q, g, o};
        src = bases[t] + (size_t)l * 262144 + (size_t)rr * 4;
    } else if (r < 458752) {
        src = wh + (size_t)l * 1048576 + (size_t)(r - 196608) * 4;
    } else if (r < 720896) {
        src = wg + (size_t)l * 1048576 + (size_t)(r - 458752) * 4;
    } else {
        src = wo + (size_t)l * 1048576 + (size_t)(r - 720896) * 4;
    }
    split4(*(const float4*)src, hi, lo, dst);
}

// ---------------------------------------------------------------------------
// bf16x3 mma.sync NT GEMM (layer GEMMs). CTA tile 128 x BN=64, 8 warps,
// K-chunk 32, cp.async double buffer, one barrier per chunk.
// EPI: 0 = store (dual-output: C2/nSplit select buffer by n0),
//      1 = C += acc, 2 = C += acc * gate (gate row stride = Ndim).
constexpr int PAD = 40;

template<int BN>
__device__ __forceinline__ void stage_chunk(
    const __nv_bfloat16* __restrict__ Ahi, const __nv_bfloat16* __restrict__ Alo,
    const __nv_bfloat16* __restrict__ Bhi, const __nv_bfloat16* __restrict__ Blo,
    int m0, int n0, int Kdim, int kt, uint32_t sbuf, int tid) {
    constexpr int OFF_ALO = 128 * PAD;
    constexpr int OFF_BHI = 256 * PAD;
    constexpr int OFF_BLO = (256 + BN) * PAD;
    #pragma unroll
    for (int it = 0; it < 2; it++) {
        int i = tid + it * 256;
        int r = i >> 2, c = (i & 3) << 3;
        size_t ga = (size_t)(m0 + r) * Kdim + kt + c;
        uint32_t d = sbuf + (uint32_t)(r * PAD + c) * 2;
        cp16(d, Ahi + ga);
        cp16(d + OFF_ALO * 2, Alo + ga);
    }
    #pragma unroll
    for (int it = 0; it < BN / 64; it++) {
        int i = tid + it * 256;
        int r = i >> 2, c = (i & 3) << 3;
        size_t gb = (size_t)(n0 + r) * Kdim + kt + c;
        uint32_t d = sbuf + (uint32_t)(r * PAD + c) * 2;
        cp16(d + OFF_BHI * 2, Bhi + gb);
        cp16(d + OFF_BLO * 2, Blo + gb);
    }
}

template<int EPI, int BN>
__global__ void __launch_bounds__(256) gemm_mma(
    const __nv_bfloat16* __restrict__ Ahi, const __nv_bfloat16* __restrict__ Alo,
    const __nv_bfloat16* __restrict__ Bhi, const __nv_bfloat16* __restrict__ Blo,
    float* __restrict__ C, float* __restrict__ C2, int nSplit,
    const float* __restrict__ gate, int Ndim, int Kdim) {
    constexpr int WNT = BN / 2;
    constexpr int NT  = WNT / 8;
    constexpr int NP  = WNT / 16;
    constexpr int OFF_ALO = 128 * PAD;
    constexpr int OFF_BHI = 256 * PAD;
    constexpr int OFF_BLO = (256 + BN) * PAD;
    constexpr int BUF_BYTES = (256 + 2 * BN) * PAD * 2;

    extern __shared__ char smc[];
    const uint32_t sbase = smem_u32(smc);
    const int tid = threadIdx.x;
    const int lane = tid & 31, wid = tid >> 5;
    const int wm = wid & 3, wn = wid >> 2;
    const int m0 = blockIdx.y * 128, n0 = blockIdx.x * BN;
    const int NC = Kdim >> 5;

    float acc[2][NT][4] = {};

    const uint32_t a_lane = (uint32_t)((lane & 15) * PAD + ((lane >> 4) << 3)) * 2;
    const uint32_t b_lane = (uint32_t)(((lane & 7) + ((lane >> 4) << 3)) * PAD
                                       + (((lane >> 3) & 1) << 3)) * 2;

    stage_chunk<BN>(Ahi, Alo, Bhi, Blo, m0, n0, Kdim, 0, sbase, tid);
    CP_COMMIT();

    for (int c = 0; c < NC; c++) {
        const int buf = c & 1;
        CP_WAIT(0);          // chunk c resident in smem
        __syncthreads();     // all warps done with compute(c-1); chunk c visible
        if (c + 1 < NC) {
            stage_chunk<BN>(Ahi, Alo, Bhi, Blo, m0, n0, Kdim, (c + 1) << 5,
                            sbase + (buf ^ 1) * BUF_BYTES, tid);
            CP_COMMIT();
        }

        const uint32_t sb = sbase + buf * BUF_BYTES;
        #pragma unroll
        for (int ks = 0; ks < 32; ks += 16) {
            uint32_t ah[2][4], al[2][4], bh[NP][4], bl[NP][4];
            #pragma unroll
            for (int mt = 0; mt < 2; mt++) {
                uint32_t ar = sb + (uint32_t)(((wm * 32 + mt * 16) * PAD + ks) * 2) + a_lane;
                ldsm4(ah[mt], ar);
                ldsm4(al[mt], ar + OFF_ALO * 2);
            }
            #pragma unroll
            for (int p = 0; p < NP; p++) {
                uint32_t br = sb + (uint32_t)(((wn * WNT + p * 16) * PAD + ks) * 2) + b_lane;
                ldsm4(bh[p], br + OFF_BHI * 2);
                ldsm4(bl[p], br + OFF_BLO * 2);
            }
            #pragma unroll
            for (int mt = 0; mt < 2; mt++)
                #pragma unroll
                for (int j = 0; j < NT; j++) {
                    const uint32_t* bhp = &bh[j >> 1][(j & 1) * 2];
                    const uint32_t* blp = &bl[j >> 1][(j & 1) * 2];
                    mma16816(acc[mt][j], ah[mt], bhp);
                    mma16816(acc[mt][j], ah[mt], blp);
                    mma16816(acc[mt][j], al[mt], bhp);
                }
        }
    }

    // dual-output select (uniform per CTA; BN=64 never straddles nSplit)
    float* Cout = C;
    int nbase = n0;
    if (EPI == 0 && C2 != nullptr && n0 >= nSplit) { Cout = C2; nbase = n0 - nSplit; }

    #pragma unroll
    for (int mt = 0; mt < 2; mt++) {
        int row = m0 + wm * 32 + mt * 16 + (lane >> 2);
        #pragma unroll
        for (int j = 0; j < NT; j++) {
            int col = nbase + wn * WNT + j * 8 + (lane & 3) * 2;
            float* c0 = Cout + (size_t)row * Ndim + col;
            float* c1 = Cout + (size_t)(row + 8) * Ndim + col;
            if (EPI == 1) {
                c0[0] += acc[mt][j][0]; c0[1] += acc[mt][j][1];
                c1[0] += acc[mt][j][2]; c1[1] += acc[mt][j][3];
            } else if (EPI == 2) {
                const float* g0 = gate + (size_t)row * Ndim + col;
                const float* g1 = gate + (size_t)(row + 8) * Ndim + col;
                c0[0] += acc[mt][j][0] * g0[0]; c0[1] += acc[mt][j][1] * g0[1];
                c1[0] += acc[mt][j][2] * g1[0]; c1[1] += acc[mt][j][3] * g1[1];
            } else {
                *(float2*)c0 = make_float2(acc[mt][j][0], acc[mt][j][1]);
                *(float2*)c1 = make_float2(acc[mt][j][2], acc[mt][j][3]);
            }
        }
    }
}

constexpr int GSMEM64 = 2 * (256 + 128) * PAD * 2;   // 61440

// ---------------------------------------------------------------------------
// fp16 1-product logits GEMM: C = A @ B^T, both single-rounded fp16.
// CTA tile 128 x 128, 8 warps (warp 32x64), K-chunk 32, double buffer,
// one barrier per chunk.
constexpr int P_OFF_B   = 128 * PAD;
constexpr int P_BUF_BYTES = (128 + 128) * PAD * 2;   // 20480
constexpr int P_GSMEM = 2 * P_BUF_BYTES;             // 40960

__device__ __forceinline__ void stage_1p(
    const __half* __restrict__ Ah, const __half* __restrict__ Bh,
    int m0, int n0, int Kdim, int kt, uint32_t sbuf, int tid) {
    #pragma unroll
    for (int it = 0; it < 2; it++) {
        int i = tid + it * 256;
        int r = i >> 2, c = (i & 3) << 3;
        size_t ga = (size_t)(m0 + r) * Kdim + kt + c;
        cp16(sbuf + (uint32_t)(r * PAD + c) * 2, Ah + ga);
    }
    #pragma unroll
    for (int it = 0; it < 2; it++) {
        int i = tid + it * 256;
        int r = i >> 2, c = (i & 3) << 3;
        size_t gb = (size_t)(n0 + r) * Kdim + kt + c;
        cp16(sbuf + P_OFF_B * 2 + (uint32_t)(r * PAD + c) * 2, Bh + gb);
    }
}

__global__ void __launch_bounds__(256) gemm_1p(
    const __half* __restrict__ Ah, const __half* __restrict__ Bh,
    float* __restrict__ C, int Ndim, int Kdim) {
    extern __shared__ char smc[];
    const uint32_t sbase = smem_u32(smc);
    const int tid = threadIdx.x;
    const int lane = tid & 31, wid = tid >> 5;
    const int wm = wid & 3, wn = wid >> 2;
    const int m0 = blockIdx.y * 128, n0 = blockIdx.x * 128;
    const int NC = Kdim >> 5;

    float acc[2][8][4] = {};

    const uint32_t a_lane = (uint32_t)((lane & 15) * PAD + ((lane >> 4) << 3)) * 2;
    const uint32_t b_lane = (uint32_t)(((lane & 7) + ((lane >> 4) << 3)) * PAD
                                       + (((lane >> 3) & 1) << 3)) * 2;

    stage_1p(Ah, Bh, m0, n0, Kdim, 0, sbase, tid);
    CP_COMMIT();

    for (int c = 0; c < NC; c++) {
        const int buf = c & 1;
        CP_WAIT(0);
        __syncthreads();
        if (c + 1 < NC) {
            stage_1p(Ah, Bh, m0, n0, Kdim, (c + 1) << 5,
                     sbase + (buf ^ 1) * P_BUF_BYTES, tid);
            CP_COMMIT();
        }

        const uint32_t sb = sbase + buf * P_BUF_BYTES;
        #pragma unroll
        for (int ks = 0; ks < 32; ks += 16) {
            uint32_t ah[2][4], bw[4][4];
            #pragma unroll
            for (int mt = 0; mt < 2; mt++) {
                uint32_t ar = sb + (uint32_t)(((wm * 32 + mt * 16) * PAD + ks) * 2) + a_lane;
                ldsm4(ah[mt], ar);
            }
            #pragma unroll
            for (int p = 0; p < 4; p++) {
                uint32_t br = sb + (uint32_t)(((wn * 64 + p * 16) * PAD + ks) * 2) + b_lane;
                ldsm4(bw[p], br + P_OFF_B * 2);
            }
            #pragma unroll
            for (int mt = 0; mt < 2; mt++)
                #pragma unroll
                for (int j = 0; j < 8; j++) {
                    const uint32_t* bp = &bw[j >> 1][(j & 1) * 2];
                    mma16816h(acc[mt][j], ah[mt], bp);
                }
        }
    }

    #pragma unroll
    for (int mt = 0; mt < 2; mt++) {
        int row = m0 + wm * 32 + mt * 16 + (lane >> 2);
        #pragma unroll
        for (int j = 0; j < 8; j++) {
            int col = n0 + wn * 64 + j * 8 + (lane & 3) * 2;
            *(float2*)(C + (size_t)row * Ndim + col) =
                make_float2(acc[mt][j][0], acc[mt][j][1]);
            *(float2*)(C + (size_t)(row + 8) * Ndim + col) =
                make_float2(acc[mt][j][2], acc[mt][j][3]);
        }
    }
}

// ---------------------------------------------------------------------------
// Embedding gather
__global__ void embed_k(const int* __restrict__ tok,
                        const float* __restrict__ emb,
                        float* __restrict__ x) {
    int i = blockIdx.x * blockDim.x + threadIdx.x;
    int row = i / (cD / 4);
    int c   = i % (cD / 4);
    int t = tok[row];
    ((float4*)x)[i] = ((const float4*)(emb + (size_t)t * cD))[c];
}

// RMSNorm + lambda fused: h = rmsnorm(x)*w -> (hi,lo) bf16; nl = logsigmoid(h.lw)
__global__ void rms_lambda_k(const float* __restrict__ x,
                             const float* __restrict__ w,
                             const float* __restrict__ lw,
                             __nv_bfloat16* __restrict__ hi,
                             __nv_bfloat16* __restrict__ lo,
                             float* __restrict__ nlout) {
    int row = blockIdx.x;
    int tid = threadIdx.x;
    float4 v = ((const float4*)(x + (size_t)row * cD))[tid];
    float ss = v.x * v.x + v.y * v.y + v.z * v.z + v.w * v.w;
    #pragma unroll
    for (int o = 16; o; o >>= 1) ss += __shfl_xor_sync(0xFFFFFFFFu, ss, o);
    __shared__ float sred[4];
    if ((tid & 31) == 0) sred[tid >> 5] = ss;
    __syncthreads();
    float sc = rsqrtf((sred[0] + sred[1] + sred[2] + sred[3]) * (1.0f / cD) + 1e-6f);
    float4 wv = ((const float4*)w)[tid];
    float4 h;
    h.x = v.x * sc * wv.x; h.y = v.y * sc * wv.y;
    h.z = v.z * sc * wv.z; h.w = v.w * sc * wv.w;
    split4(h, hi, lo, (size_t)row * cD + tid * 4);
    float4 lv = ((const float4*)lw)[tid];
    float d = h.x * lv.x + h.y * lv.y + h.z * lv.z + h.w * lv.w;
    #pragma unroll
    for (int o = 16; o; o >>= 1) d += __shfl_xor_sync(0xFFFFFFFFu, d, o);
    __shared__ float dred[4];
    if ((tid & 31) == 0) dred[tid >> 5] = d;
    __syncthreads();
    if (tid == 0) {
        float z = dred[0] + dred[1] + dred[2] + dred[3];
        nlout[row] = (z >= 0.f) ? -log1pf(expf(-z)) : (z - log1pf(expf(z)));
    }
}

// RMSNorm -> bf16 (hi,lo)
__global__ void rms_cvt_k(const float* __restrict__ x,
                          const float* __restrict__ w,
                          __nv_bfloat16* __restrict__ hi,
                          __nv_bfloat16* __restrict__ lo) {
    int row = blockIdx.x;
    int tid = threadIdx.x;
    float4 v = ((const float4*)(x + (size_t)row * cD))[tid];
    float ss = v.x * v.x + v.y * v.y + v.z * v.z + v.w * v.w;
    #pragma unroll
    for (int o = 16; o; o >>= 1) ss += __shfl_xor_sync(0xFFFFFFFFu, ss, o);
    __shared__ float sred[4];
    if ((tid & 31) == 0) sred[tid >> 5] = ss;
    __syncthreads();
    float sc = rsqrtf((sred[0] + sred[1] + sred[2] + sred[3]) * (1.0f / cD) + 1e-6f);
    float4 wv = ((const float4*)w)[tid];
    float4 h;
    h.x = v.x * sc * wv.x; h.y = v.y * sc * wv.y;
    h.z = v.z * sc * wv.z; h.w = v.w * sc * wv.w;
    split4(h, hi, lo, (size_t)row * cD + tid * 4);
}

// RMSNorm -> single fp16 (logits activation)
__global__ void rms_cvt_f16s_k(const float* __restrict__ x,
                               const float* __restrict__ w,
                               __half* __restrict__ h16) {
    int row = blockIdx.x;
    int tid = threadIdx.x;
    float4 v = ((const float4*)(x + (size_t)row * cD))[tid];
    float ss = v.x * v.x + v.y * v.y + v.z * v.z + v.w * v.w;
    #pragma unroll
    for (int o = 16; o; o >>= 1) ss += __shfl_xor_sync(0xFFFFFFFFu, ss, o);
    __shared__ float sred[4];
    if ((tid & 31) == 0) sred[tid >> 5] = ss;
    __syncthreads();
    float sc = rsqrtf((sred[0] + sred[1] + sred[2] + sred[3]) * (1.0f / cD) + 1e-6f);
    float4 wv = ((const float4*)w)[tid];
    __half2* H = (__half2*)(h16 + (size_t)row * cD + tid * 4);
    H[0] = __halves2half2(__float2half_rn(v.x * sc * wv.x),
                          __float2half_rn(v.y * sc * wv.y));
    H[1] = __halves2half2(__float2half_rn(v.z * sc * wv.z),
                          __float2half_rn(v.w * sc * wv.w));
}

// Windowed decay attention with one-shot liveness scan.
// Fused epilogue: out = silu(attn_out) -> bf16 (hi,lo) written to Ahi/Alo.
__global__ void __launch_bounds__(256) attn_k(const float* __restrict__ Q,
                                              const float* __restrict__ NL,
                                              __nv_bfloat16* __restrict__ hi,
                                              __nv_bfloat16* __restrict__ lo) {
    __shared__ float q_sm[16][64];
    __shared__ float w_sm[16][64];
    __shared__ float nl_sm[16];
    __shared__ int minLive;

    int b  = blockIdx.z;
    int s0 = blockIdx.y * 64;
    int d0 = blockIdx.x * 64;
    int tid = threadIdx.x;
    int tx = tid & 15;
    int ty = tid >> 4;

    float acc[4][4] = {};
    const float* Qb  = Q  + (size_t)b * cS * cD;
    const float* NLb = NL + (size_t)b * cS;

    int t_lo = s0 - 1024; if (t_lo < 0) t_lo = 0;
    int t_hi = s0 + 63;
    int n_tiles = (t_hi - t_lo + 16) >> 4;

    if (tid == 0) minLive = n_tiles - 1;
    __syncthreads();
    if (tid < n_tiles) {
        int t0 = t_lo + tid * 16;
        int live;
        if (t0 + 15 >= s0) {
            live = 1;
        } else {
            float mx = -1e30f;
            #pragma unroll 4
            for (int k = 0; k < 16; k++) mx = fmaxf(mx, NLb[t0 + k]);
            live = (mx * (float)(s0 - (t0 + 15)) > -27.6f);
        }
        if (live) atomicMin(&minLive, tid);
    }
    __syncthreads();
    int t_start = t_lo + minLive * 16;

    for (int t0 = t_start; t0 <= t_hi; t0 += 16) {
        if (tid < 16) {
            int t = t0 + tid;
            nl_sm[tid] = NLb[t < cS ? t : (cS - 1)];
        }
        {
            int k  = tid >> 4;
            int dc = (tid & 15) << 2;
            int t = t0 + k; if (t > cS - 1) t = cS - 1;
            float4 qv = *(const float4*)(Qb + (size_t)t * cD + d0 + dc);
            *(float4*)&q_sm[k][dc] = qv;
        }
        __syncthreads();
        #pragma unroll
        for (int j = 0; j < 4; j++) {
            int idx = tid + j * 256;
            int k  = idx >> 6;
            int sl = idx & 63;
            int t = t0 + k, s = s0 + sl;
            float w = 0.f;
            if (t <= s) w = __expf(nl_sm[k] * (float)(s - t));
            w_sm[k][sl] = w;
        }
        __syncthreads();

        #pragma unroll
        for (int k = 0; k < 16; k++) {
            float4 qv = *(const float4*)&q_sm[k][tx * 4];
            float wv0 = w_sm[k][ty * 4 + 0];
            float wv1 = w_sm[k][ty * 4 + 1];
            float wv2 = w_sm[k][ty * 4 + 2];
            float wv3 = w_sm[k][ty * 4 + 3];
            acc[0][0] += wv0 * qv.x; acc[0][1] += wv0 * qv.y; acc[0][2] += wv0 * qv.z; acc[0][3] += wv0 * qv.w;
            acc[1][0] += wv1 * qv.x; acc[1][1] += wv1 * qv.y; acc[1][2] += wv1 * qv.z; acc[1][3] += wv1 * qv.w;
            acc[2][0] += wv2 * qv.x; acc[2][1] += wv2 * qv.y; acc[2][2] += wv2 * qv.z; acc[2][3] += wv2 * qv.w;
            acc[3][0] += wv3 * qv.x; acc[3][1] += wv3 * qv.y; acc[3][2] += wv3 * qv.z; acc[3][3] += wv3 * qv.w;
        }
        __syncthreads();
    }

    #pragma unroll
    for (int i = 0; i < 4; i++) {
        float4 o4;
        o4.x = acc[i][0] / (1.f + expf(-acc[i][0]));
        o4.y = acc[i][1] / (1.f + expf(-acc[i][1]));
        o4.z = acc[i][2] / (1.f + expf(-acc[i][2]));
        o4.w = acc[i][3] / (1.f + expf(-acc[i][3]));
        split4(o4, hi, lo,
               (size_t)(b * cS + s0 + ty * 4 + i) * cD + d0 + tx * 4);
    }
}

// fh * silu(fg) -> bf16 (hi, lo)
__global__ void mulsilu_cvt_k(const float* __restrict__ fh,
                              const float* __restrict__ fg,
                              __nv_bfloat16* __restrict__ hi,
                              __nv_bfloat16* __restrict__ lo) {
    int i = blockIdx.x * blockDim.x + threadIdx.x;
    float4 h = ((const float4*)fh)[i];
    float4 g = ((const float4*)fg)[i];
    h.x *= g.x / (1.f + expf(-g.x));
    h.y *= g.y / (1.f + expf(-g.y));
    h.z *= g.z / (1.f + expf(-g.z));
    h.w *= g.w / (1.f + expf(-g.w));
    split4(h, hi, lo, (size_t)i * 4);
}

// ---------------------------------------------------------------------------
extern "C" void kernel_launch(void* const* d_in, const int* in_sizes, int n_in,
                              void* d_out, int out_size) {
    const int*   tokens       = (const int*)  d_in[0];
    const float* emb          = (const float*)d_in[1];
    const float* decay_norm_w = (const float*)d_in[2];
    const float* lambda_w     = (const float*)d_in[3];
    const float* quantity_w   = (const float*)d_in[4];
    const float* gate_w       = (const float*)d_in[5];
    const float* output_w     = (const float*)d_in[6];
    const float* ffn_norm_w   = (const float*)d_in[7];
    const float* w_h          = (const float*)d_in[8];
    const float* w_g          = (const float*)d_in[9];
    const float* w_o          = (const float*)d_in[10];
    const float* out_norm_w   = (const float*)d_in[11];
    float* out = (float*)d_out;

    float *X, *Q, *G1, *FH, *FG, *NL;
    cudaGetSymbolAddress((void**)&X,  gX);
    cudaGetSymbolAddress((void**)&Q,  gQ);
    cudaGetSymbolAddress((void**)&G1, gG1);
    cudaGetSymbolAddress((void**)&FH, gFH);
    cudaGetSymbolAddress((void**)&FG, gFG);
    cudaGetSymbolAddress((void**)&NL, gNL);
    __nv_bfloat16 *Whi, *Wlo, *Ahi, *Alo;
    cudaGetSymbolAddress((void**)&Whi, gWhi);
    cudaGetSymbolAddress((void**)&Wlo, gWlo);
    cudaGetSymbolAddress((void**)&Ahi, gAhi);
    cudaGetSymbolAddress((void**)&Alo, gAlo);

    static bool attr_set = false;
    if (!attr_set) {
        cudaFuncSetAttribute(gemm_mma<0, 64>, cudaFuncAttributeMaxDynamicSharedMemorySize, GSMEM64);
        cudaFuncSetAttribute(gemm_mma<1, 64>, cudaFuncAttributeMaxDynamicSharedMemorySize, GSMEM64);
        cudaFuncSetAttribute(gemm_mma<2, 64>, cudaFuncAttributeMaxDynamicSharedMemorySize, GSMEM64);
        cudaFuncSetAttribute(gemm_1p,         cudaFuncAttributeMaxDynamicSharedMemorySize, P_GSMEM);
        attr_set = true;
    }

    // ---- weight conversion (2 launches) ---------------------------------
    // emb -> fp16 single (stored in gWhi emb region, reinterpreted)
    cvt_f16_k<<<(int)(W_EMB_SZ / 4 + 255) / 256, 256>>>(emb, (__half*)Whi,
                                                        (int)(W_EMB_SZ / 4));
    wcvt_layers_k<<<(cL * L4 + 255) / 256, 256>>>(quantity_w, gate_w, output_w,
                                                  w_h, w_g, w_o, Whi, Wlo);

    const int EW_D = (cM * cD / 4) / 256;
    const int EW_H = (cM * cH / 4) / 256;

    embed_k<<<EW_D, 256>>>(tokens, emb, X);

    for (int l = 0; l < cL; l++) {
        size_t base = W_EMB_SZ + (size_t)l * W_LAYER_SZ;
        size_t oQG = base;                         // Q | G adjacent (1024 x 512)
        size_t oO  = base + 2 * (size_t)cD * cD;
        size_t oWHG = base + 3 * (size_t)cD * cD;  // WH | WG adjacent (4096 x 512)
        size_t oWO = oWHG + 2 * (size_t)cH * cD;

        rms_lambda_k<<<cM, 128>>>(X, decay_norm_w + (size_t)l * cD,
                                  lambda_w + (size_t)l * cD, Ahi, Alo, NL);
        // fused Q+gate projection, dual-output -> Q (cols 0..511), G1 (512..1023)
        gemm_mma<0, 64><<<dim3(1024 / 64, cM / 128), 256, GSMEM64>>>(
            Ahi, Alo, Whi + oQG, Wlo + oQG, Q, G1, cD, nullptr, cD, cD);
        // attention with fused silu+split epilogue -> Ahi/Alo directly
        attn_k<<<dim3(cD / 64, cS / 64, cB), 256>>>(Q, NL, Ahi, Alo);
        // O-projection with fused gated residual: X += (silu(O) @ Wo^T) * G1
        gemm_mma<2, 64><<<dim3(cD / 64, cM / 128), 256, GSMEM64>>>(
            Ahi, Alo, Whi + oO, Wlo + oO, X, nullptr, 0, G1, cD, cD);
        rms_cvt_k<<<cM, 128>>>(X, ffn_norm_w + (size_t)l * cD, Ahi, Alo);
        // fused FFN up+gate, dual-output -> FH, FG
        gemm_mma<0, 64><<<dim3(4096 / 64, cM / 128), 256, GSMEM64>>>(
            Ahi, Alo, Whi + oWHG, Wlo + oWHG, FH, FG, cH, nullptr, cH, cD);
        mulsilu_cvt_k<<<EW_H, 256>>>(FH, FG, Ahi, Alo);
        gemm_mma<1, 64><<<dim3(cD / 64, cM / 128), 256, GSMEM64>>>(
            Ahi, Alo, Whi + oWO, Wlo + oWO, X, nullptr, 0, nullptr, cD, cH);
    }

    // logits: fp16 1-product (A single fp16, emb single fp16)
    rms_cvt_f16s_k<<<cM, 128>>>(X, out_norm_w, (__half*)Ahi);
    gemm_1p<<<dim3(cV / 128, cM / 128), 256, P_GSMEM>>>(
        (__half*)Ahi, (__half*)Whi, out, cV, cD);
}